// round 7
// baseline (speedup 1.0000x reference)
#include <cuda_runtime.h>
#include <cuda_bf16.h>

#define N_NODES 100000
#define IN_F    512
#define HID     16

// ---------------- scratch (static device globals; no allocation) ------------
__device__ __align__(16) float g_dis [N_NODES];        // 0.4 MB
__device__ __align__(16) float g_h   [N_NODES * HID];  // 6.4 MB (h1 then h2)
__device__ __align__(16) float g_agg1[N_NODES * HID];  // 6.4 MB
__device__ int g_ei64;   // 1 if edge_index is int64, 0 if int32

// ---------------- helpers ---------------------------------------------------
__device__ __forceinline__ void red_add_v4(float* p, float a, float b, float c, float d) {
    size_t gp = __cvta_generic_to_global(p);
    asm volatile("red.global.add.v4.f32 [%0], {%1,%2,%3,%4};"
                 :: "l"(gp), "f"(a), "f"(b), "f"(c), "f"(d) : "memory");
}

__device__ __forceinline__ int load_idx(const void* ei, size_t elem, int is64) {
    if (is64) return (int)((const long long*)ei)[elem];
    return ((const int*)ei)[elem];
}

// ---------------- edge-index dtype probe -------------------------------------
__global__ void detect_ei_kernel(const int* __restrict__ ei32) {
    int nz = 0;
    for (int i = threadIdx.x; i < 256; i += 32)
        if (ei32[2 * i + 1] != 0) nz = 1;
    nz = __any_sync(0xffffffffu, nz);
    if (threadIdx.x == 0) g_ei64 = nz ? 0 : 1;
}

// ---------------- degree / norm ---------------------------------------------
__global__ void init_deg_kernel(int n) {
    int i = blockIdx.x * blockDim.x + threadIdx.x;
    if (i < n) g_dis[i] = 1.0f;               // self-loop contributes 1 to deg
}

__global__ void count_deg_kernel(const void* __restrict__ ei, int E, int n) {
    int e = blockIdx.x * blockDim.x + threadIdx.x;
    if (e >= E) return;
    int is64 = g_ei64;
    int d = load_idx(ei, (size_t)E + e, is64);
    if ((unsigned)d < (unsigned)n)
        atomicAdd(&g_dis[d], 1.0f);
}

__global__ void finalize_dis_kernel(int n) {
    int i = blockIdx.x * blockDim.x + threadIdx.x;
    if (i < n) g_dis[i] = rsqrtf(g_dis[i]);   // deg >= 1 always (self loop)
}

// ---------------- GEMM1: h1 = x @ W1 ; agg1 = dis^2 * h1 (self-loop init) ---
// ZERO local arrays: 16 named float4 accumulators manipulated via macros.
__device__ __forceinline__ void store_row1(int r, int n,
                                           float4 b0, float4 b1, float4 b2, float4 b3) {
    if (r >= n) return;
    float d = g_dis[r];
    float d2 = d * d;
    float4* hp = (float4*)(g_h   + (size_t)r * HID);
    float4* ap = (float4*)(g_agg1 + (size_t)r * HID);
    hp[0] = b0; hp[1] = b1; hp[2] = b2; hp[3] = b3;
    ap[0] = make_float4(d2*b0.x, d2*b0.y, d2*b0.z, d2*b0.w);
    ap[1] = make_float4(d2*b1.x, d2*b1.y, d2*b1.z, d2*b1.w);
    ap[2] = make_float4(d2*b2.x, d2*b2.y, d2*b2.z, d2*b2.w);
    ap[3] = make_float4(d2*b3.x, d2*b3.y, d2*b3.z, d2*b3.w);
}

__global__ __launch_bounds__(256) void gemm1_kernel(
    const float* __restrict__ x, const float* __restrict__ W1, int n)
{
    __shared__ float w_s[HID * IN_F];         // w_s[j*512 + k] = W1[k][j], 32 KB
    for (int idx = threadIdx.x; idx < IN_F * HID; idx += blockDim.x) {
        int k = idx >> 4, j = idx & 15;
        w_s[j * IN_F + k] = W1[idx];
    }
    __syncthreads();

    int warp = threadIdx.x >> 5;
    int lane = threadIdx.x & 31;
    int r0 = (blockIdx.x * 8 + warp) * 4;
    if (r0 >= n) return;
    int rl = min(r0 + 3, n - 1);

    const float* xr0 = x + (size_t)r0 * IN_F;
    const float* xr1 = x + (size_t)min(r0 + 1, rl) * IN_F;
    const float* xr2 = x + (size_t)min(r0 + 2, rl) * IN_F;
    const float* xr3 = x + (size_t)rl * IN_F;

    float4 z = make_float4(0.f, 0.f, 0.f, 0.f);
    float4 a0_0=z, a0_1=z, a0_2=z, a0_3=z;
    float4 a1_0=z, a1_1=z, a1_2=z, a1_3=z;
    float4 a2_0=z, a2_1=z, a2_2=z, a2_3=z;
    float4 a3_0=z, a3_1=z, a3_2=z, a3_3=z;

#pragma unroll 4
    for (int i = 0; i < IN_F / 32; i++) {
        int k = lane + (i << 5);
        float x0 = xr0[k], x1 = xr1[k], x2 = xr2[k], x3 = xr3[k];
#define GSTEP(c) { \
        float w0 = w_s[(4*(c)+0)*IN_F + k]; \
        float w1 = w_s[(4*(c)+1)*IN_F + k]; \
        float w2 = w_s[(4*(c)+2)*IN_F + k]; \
        float w3 = w_s[(4*(c)+3)*IN_F + k]; \
        a0_##c.x += x0*w0; a0_##c.y += x0*w1; a0_##c.z += x0*w2; a0_##c.w += x0*w3; \
        a1_##c.x += x1*w0; a1_##c.y += x1*w1; a1_##c.z += x1*w2; a1_##c.w += x1*w3; \
        a2_##c.x += x2*w0; a2_##c.y += x2*w1; a2_##c.z += x2*w2; a2_##c.w += x2*w3; \
        a3_##c.x += x3*w0; a3_##c.y += x3*w1; a3_##c.z += x3*w2; a3_##c.w += x3*w3; }
        GSTEP(0) GSTEP(1) GSTEP(2) GSTEP(3)
#undef GSTEP
    }

    // butterfly: every lane ends with the full sums
#define RED(v) { v.x += __shfl_xor_sync(0xffffffffu, v.x, off); \
                 v.y += __shfl_xor_sync(0xffffffffu, v.y, off); \
                 v.z += __shfl_xor_sync(0xffffffffu, v.z, off); \
                 v.w += __shfl_xor_sync(0xffffffffu, v.w, off); }
#pragma unroll
    for (int off = 16; off; off >>= 1) {
        RED(a0_0) RED(a0_1) RED(a0_2) RED(a0_3)
        RED(a1_0) RED(a1_1) RED(a1_2) RED(a1_3)
        RED(a2_0) RED(a2_1) RED(a2_2) RED(a2_3)
        RED(a3_0) RED(a3_1) RED(a3_2) RED(a3_3)
    }
#undef RED

    if (lane == 0) store_row1(r0 + 0, n, a0_0, a0_1, a0_2, a0_3);
    if (lane == 1) store_row1(r0 + 1, n, a1_0, a1_1, a1_2, a1_3);
    if (lane == 2) store_row1(r0 + 2, n, a2_0, a2_1, a2_2, a2_3);
    if (lane == 3) store_row1(r0 + 3, n, a3_0, a3_1, a3_2, a3_3);
}

// ---------------- edge scatter: agg[dst] += dis[src]*dis[dst] * h[src] ------
// h is always g_h (referenced internally); agg target differs per layer.
__device__ __forceinline__ void scatter_body(const void* ei, float* agg, int E, int n, int e) {
    int is64 = g_ei64;
    int s = load_idx(ei, (size_t)e, is64);
    int d = load_idx(ei, (size_t)E + e, is64);
    if ((unsigned)s >= (unsigned)n) return;
    if ((unsigned)d >= (unsigned)n) return;
    float nrm = g_dis[s] * g_dis[d];
    const float4* hp = (const float4*)(g_h + (size_t)s * HID);
    float4 v0 = hp[0], v1 = hp[1], v2 = hp[2], v3 = hp[3];
    float* ap = agg + (size_t)d * HID;
    red_add_v4(ap +  0, nrm*v0.x, nrm*v0.y, nrm*v0.z, nrm*v0.w);
    red_add_v4(ap +  4, nrm*v1.x, nrm*v1.y, nrm*v1.z, nrm*v1.w);
    red_add_v4(ap +  8, nrm*v2.x, nrm*v2.y, nrm*v2.z, nrm*v2.w);
    red_add_v4(ap + 12, nrm*v3.x, nrm*v3.y, nrm*v3.z, nrm*v3.w);
}

__global__ void scatter1_kernel(const void* __restrict__ ei, int E, int n) {
    int e = blockIdx.x * blockDim.x + threadIdx.x;
    if (e >= E) return;
    scatter_body(ei, g_agg1, E, n, e);
}

__global__ void scatter2_kernel(const void* __restrict__ ei, float* __restrict__ out,
                                int E, int n) {
    int e = blockIdx.x * blockDim.x + threadIdx.x;
    if (e >= E) return;
    scatter_body(ei, out, E, n, e);
}

// ---------------- layer 2: h2 = relu(agg1+b1) @ W2 ; out = dis^2*h2 (agg2 init)
__global__ void layer2_kernel(const float* __restrict__ b1,
                              const float* __restrict__ W2,
                              float* __restrict__ out, int n)
{
    __shared__ float W2s[HID * HID];
    __shared__ float b1s[HID];
    if (threadIdx.x < HID * HID) W2s[threadIdx.x] = W2[threadIdx.x];
    if (threadIdx.x < HID)       b1s[threadIdx.x] = b1[threadIdx.x];
    __syncthreads();

    int i = blockIdx.x * blockDim.x + threadIdx.x;
    if (i >= n) return;

    const float4* ap = (const float4*)(g_agg1 + (size_t)i * HID);
    float4 v0 = ap[0], v1 = ap[1], v2 = ap[2], v3 = ap[3];
    v0.x = fmaxf(v0.x + b1s[0],  0.f); v0.y = fmaxf(v0.y + b1s[1],  0.f);
    v0.z = fmaxf(v0.z + b1s[2],  0.f); v0.w = fmaxf(v0.w + b1s[3],  0.f);
    v1.x = fmaxf(v1.x + b1s[4],  0.f); v1.y = fmaxf(v1.y + b1s[5],  0.f);
    v1.z = fmaxf(v1.z + b1s[6],  0.f); v1.w = fmaxf(v1.w + b1s[7],  0.f);
    v2.x = fmaxf(v2.x + b1s[8],  0.f); v2.y = fmaxf(v2.y + b1s[9],  0.f);
    v2.z = fmaxf(v2.z + b1s[10], 0.f); v2.w = fmaxf(v2.w + b1s[11], 0.f);
    v3.x = fmaxf(v3.x + b1s[12], 0.f); v3.y = fmaxf(v3.y + b1s[13], 0.f);
    v3.z = fmaxf(v3.z + b1s[14], 0.f); v3.w = fmaxf(v3.w + b1s[15], 0.f);

#define DOT(J) ( v0.x*W2s[ 0*HID+(J)] + v0.y*W2s[ 1*HID+(J)] + v0.z*W2s[ 2*HID+(J)] + v0.w*W2s[ 3*HID+(J)] \
               + v1.x*W2s[ 4*HID+(J)] + v1.y*W2s[ 5*HID+(J)] + v1.z*W2s[ 6*HID+(J)] + v1.w*W2s[ 7*HID+(J)] \
               + v2.x*W2s[ 8*HID+(J)] + v2.y*W2s[ 9*HID+(J)] + v2.z*W2s[10*HID+(J)] + v2.w*W2s[11*HID+(J)] \
               + v3.x*W2s[12*HID+(J)] + v3.y*W2s[13*HID+(J)] + v3.z*W2s[14*HID+(J)] + v3.w*W2s[15*HID+(J)] )
    float4 s0 = make_float4(DOT(0),  DOT(1),  DOT(2),  DOT(3));
    float4 s1 = make_float4(DOT(4),  DOT(5),  DOT(6),  DOT(7));
    float4 s2 = make_float4(DOT(8),  DOT(9),  DOT(10), DOT(11));
    float4 s3 = make_float4(DOT(12), DOT(13), DOT(14), DOT(15));
#undef DOT

    float dis = g_dis[i];
    float d2 = dis * dis;
    float4* hp = (float4*)(g_h + (size_t)i * HID);
    float4* gp = (float4*)(out + (size_t)i * HID);
    hp[0] = s0; hp[1] = s1; hp[2] = s2; hp[3] = s3;
    gp[0] = make_float4(d2*s0.x, d2*s0.y, d2*s0.z, d2*s0.w);
    gp[1] = make_float4(d2*s1.x, d2*s1.y, d2*s1.z, d2*s1.w);
    gp[2] = make_float4(d2*s2.x, d2*s2.y, d2*s2.z, d2*s2.w);
    gp[3] = make_float4(d2*s3.x, d2*s3.y, d2*s3.z, d2*s3.w);
}

// ---------------- final: out = log_softmax(out + b2)  (in place) -------------
__global__ void final_kernel(const float* __restrict__ b2,
                             float* __restrict__ out, int n)
{
    __shared__ float b2s[HID];
    if (threadIdx.x < HID) b2s[threadIdx.x] = b2[threadIdx.x];
    __syncthreads();

    int i = blockIdx.x * blockDim.x + threadIdx.x;
    if (i >= n) return;

    float4* op = (float4*)(out + (size_t)i * HID);
    float4 v0 = op[0], v1 = op[1], v2 = op[2], v3 = op[3];
    v0.x += b2s[0];  v0.y += b2s[1];  v0.z += b2s[2];  v0.w += b2s[3];
    v1.x += b2s[4];  v1.y += b2s[5];  v1.z += b2s[6];  v1.w += b2s[7];
    v2.x += b2s[8];  v2.y += b2s[9];  v2.z += b2s[10]; v2.w += b2s[11];
    v3.x += b2s[12]; v3.y += b2s[13]; v3.z += b2s[14]; v3.w += b2s[15];

    float m = fmaxf(fmaxf(fmaxf(v0.x, v0.y), fmaxf(v0.z, v0.w)),
             fmaxf(fmaxf(fmaxf(v1.x, v1.y), fmaxf(v1.z, v1.w)),
             fmaxf(fmaxf(fmaxf(v2.x, v2.y), fmaxf(v2.z, v2.w)),
                   fmaxf(fmaxf(v3.x, v3.y), fmaxf(v3.z, v3.w)))));

    float ssum = expf(v0.x - m) + expf(v0.y - m) + expf(v0.z - m) + expf(v0.w - m)
               + expf(v1.x - m) + expf(v1.y - m) + expf(v1.z - m) + expf(v1.w - m)
               + expf(v2.x - m) + expf(v2.y - m) + expf(v2.z - m) + expf(v2.w - m)
               + expf(v3.x - m) + expf(v3.y - m) + expf(v3.z - m) + expf(v3.w - m);
    float lse = m + logf(ssum);

    op[0] = make_float4(v0.x - lse, v0.y - lse, v0.z - lse, v0.w - lse);
    op[1] = make_float4(v1.x - lse, v1.y - lse, v1.z - lse, v1.w - lse);
    op[2] = make_float4(v2.x - lse, v2.y - lse, v2.z - lse, v2.w - lse);
    op[3] = make_float4(v3.x - lse, v3.y - lse, v3.z - lse, v3.w - lse);
}

// ---------------- launch ------------------------------------------------------
extern "C" void kernel_launch(void* const* d_in, const int* in_sizes, int n_in,
                              void* d_out, int out_size)
{
    // Bind inputs by ELEMENT COUNT (unique per tensor).
    const float* x  = nullptr;
    const void*  ei = nullptr;
    const float* W1 = nullptr;
    const float* W2 = nullptr;
    const float* b1 = nullptr;
    const float* b2 = nullptr;
    long long x_elems = 0, ei_elems = 0;

    for (int i = 0; i < n_in; i++) {
        int sz = in_sizes[i];
        if (sz >= 10000000) {                 // x (51.2M f32)
            x = (const float*)d_in[i]; x_elems = sz;
        } else if (sz >= 1000000) {           // edge_index (6.4M elems, dtype probed)
            ei = d_in[i]; ei_elems = sz;
        } else if (sz == IN_F * HID) {        // W1
            W1 = (const float*)d_in[i];
        } else if (sz == HID * HID) {         // W2
            W2 = (const float*)d_in[i];
        } else if (sz == HID) {               // b1 then b2 (both zero anyway)
            if (!b1) b1 = (const float*)d_in[i];
            else     b2 = (const float*)d_in[i];
        }
    }
    if (!b2) b2 = b1;
    float* out = (float*)d_out;

    int N = (int)(x_elems / IN_F);            // 100000
    int E = (int)(ei_elems / 2);              // 3200000

    int nb_nodes = (N + 255) / 256;
    int nb_edges = (E + 255) / 256;
    int nb_gemm  = (N + 31) / 32;             // 32 rows per block

    detect_ei_kernel   <<<1, 32>>>((const int*)ei);
    init_deg_kernel    <<<nb_nodes, 256>>>(N);
    count_deg_kernel   <<<nb_edges, 256>>>(ei, E, N);
    finalize_dis_kernel<<<nb_nodes, 256>>>(N);

    gemm1_kernel       <<<nb_gemm, 256>>>(x, W1, N);
    scatter1_kernel    <<<nb_edges, 256>>>(ei, E, N);

    layer2_kernel      <<<nb_nodes, 256>>>(b1, W2, out, N);
    scatter2_kernel    <<<nb_edges, 256>>>(ei, out, E, N);

    final_kernel       <<<nb_nodes, 256>>>(b2, out, N);
}

// round 10
// speedup vs baseline: 1.1644x; 1.1644x over previous
#include <cuda_runtime.h>
#include <cuda_bf16.h>

#define N_NODES 100000
#define E_MAX   3200000
#define IN_F    512
#define HID     16
#define RP_MASK 0x3FFFFFu

// ---------------- scratch: 13.2 MB total statics (== proven-pass R7) --------
__device__ __align__(16) unsigned short g_csr_lo[E_MAX];          // 6.4 MB
__device__ __align__(16) float          g_hbuf  [N_NODES * HID];  // 6.4 MB
__device__ unsigned int g_rowptr[N_NODES];                        // 0.4 MB: end | (nlow<<22)
__device__ int g_bsum[512];
__device__ int g_ei64;

// ---------------- helpers ---------------------------------------------------
__device__ __forceinline__ int load_idx(const void* ei, size_t elem, int is64) {
    if (is64) return (int)((const long long*)ei)[elem];
    return ((const int*)ei)[elem];
}

__device__ __forceinline__ float node_dis(int i) {
    unsigned end = g_rowptr[i] & RP_MASK;
    unsigned st  = (i > 0) ? (g_rowptr[i - 1] & RP_MASK) : 0u;
    return rsqrtf((float)(end - st) + 1.0f);   // +1 = self loop
}

// ---------------- edge-index dtype probe -------------------------------------
__global__ void detect_ei_kernel(const int* __restrict__ ei32) {
    int nz = 0;
    for (int i = threadIdx.x; i < 256; i += 32)
        if (ei32[2 * i + 1] != 0) nz = 1;
    nz = __any_sync(0xffffffffu, nz);
    if (threadIdx.x == 0) g_ei64 = nz ? 0 : 1;
}

// ---------------- CSR build (cursors/counts live in d_out scratch) -----------
// scratch layout (ints): [0,n)=cnt_total  [n,2n)=cnt_low  [2n,3n)=cur_low  [3n,4n)=cur_high
__global__ void zero_scratch_kernel(int* __restrict__ sc, int n2) {
    int i = blockIdx.x * blockDim.x + threadIdx.x;
    if (i < n2) sc[i] = 0;
}

__global__ void hist_kernel(const void* __restrict__ ei, int* __restrict__ sc,
                            int E, int n) {
    int e = blockIdx.x * blockDim.x + threadIdx.x;
    if (e >= E) return;
    int is64 = g_ei64;
    int s = load_idx(ei, (size_t)e, is64);
    int d = load_idx(ei, (size_t)E + e, is64);
    if ((unsigned)s >= (unsigned)n) return;
    if ((unsigned)d >= (unsigned)n) return;
    atomicAdd(&sc[d], 1);
    if (s < 65536) atomicAdd(&sc[n + d], 1);
}

// block-local exclusive scan of cnt_total -> cur_low slot; block sums -> g_bsum
__global__ __launch_bounds__(256) void scan_block_kernel(int* __restrict__ sc, int n) {
    __shared__ int s[256];
    int i = blockIdx.x * 256 + threadIdx.x;
    int v = (i < n) ? sc[i] : 0;
    s[threadIdx.x] = v;
    __syncthreads();
#pragma unroll
    for (int off = 1; off < 256; off <<= 1) {
        int t = (threadIdx.x >= off) ? s[threadIdx.x - off] : 0;
        __syncthreads();
        s[threadIdx.x] += t;
        __syncthreads();
    }
    if (i < n) sc[2 * n + i] = s[threadIdx.x] - v;
    if (threadIdx.x == 255) g_bsum[blockIdx.x] = s[255];
}

__global__ __launch_bounds__(512) void scan_bsum_kernel(int nb) {
    __shared__ int s[512];
    int v = (threadIdx.x < nb) ? g_bsum[threadIdx.x] : 0;
    s[threadIdx.x] = v;
    __syncthreads();
#pragma unroll
    for (int off = 1; off < 512; off <<= 1) {
        int t = (threadIdx.x >= off) ? s[threadIdx.x - off] : 0;
        __syncthreads();
        s[threadIdx.x] += t;
        __syncthreads();
    }
    if (threadIdx.x < nb) g_bsum[threadIdx.x] = s[threadIdx.x] - v;
}

// finalize: cursors + packed rowptr (end | nlow<<22)
__global__ void finalize_kernel(int* __restrict__ sc, int n) {
    int i = blockIdx.x * blockDim.x + threadIdx.x;
    if (i >= n) return;
    int start = sc[2 * n + i] + g_bsum[i >> 8];
    int deg   = sc[i];
    int nlow  = sc[n + i];
    sc[2 * n + i] = start;               // cur_low
    sc[3 * n + i] = start + nlow;        // cur_high
    g_rowptr[i] = (unsigned)(start + deg) | ((unsigned)nlow << 22);
}

__global__ void fill_kernel(const void* __restrict__ ei, int* __restrict__ sc,
                            int E, int n) {
    int e = blockIdx.x * blockDim.x + threadIdx.x;
    if (e >= E) return;
    int is64 = g_ei64;
    int s = load_idx(ei, (size_t)e, is64);
    int d = load_idx(ei, (size_t)E + e, is64);
    if ((unsigned)s >= (unsigned)n) return;
    if ((unsigned)d >= (unsigned)n) return;
    int pos = (s < 65536) ? atomicAdd(&sc[2 * n + d], 1)
                          : atomicAdd(&sc[3 * n + d], 1);
    if ((unsigned)pos < (unsigned)E_MAX)
        g_csr_lo[pos] = (unsigned short)(s & 0xFFFF);
}

// ---------------- GEMM1: hbuf = hs1 = dis * (x @ W1) -------------------------
__device__ __forceinline__ void store_row1(int r, int n,
                                           float4 b0, float4 b1, float4 b2, float4 b3) {
    if (r >= n) return;
    float d = node_dis(r);
    float4* hp = (float4*)(g_hbuf + (size_t)r * HID);
    hp[0] = make_float4(d*b0.x, d*b0.y, d*b0.z, d*b0.w);
    hp[1] = make_float4(d*b1.x, d*b1.y, d*b1.z, d*b1.w);
    hp[2] = make_float4(d*b2.x, d*b2.y, d*b2.z, d*b2.w);
    hp[3] = make_float4(d*b3.x, d*b3.y, d*b3.z, d*b3.w);
}

__global__ __launch_bounds__(256) void gemm1_kernel(
    const float* __restrict__ x, const float* __restrict__ W1, int n)
{
    __shared__ float w_s[HID * IN_F];
    for (int idx = threadIdx.x; idx < IN_F * HID; idx += blockDim.x) {
        int k = idx >> 4, j = idx & 15;
        w_s[j * IN_F + k] = W1[idx];
    }
    __syncthreads();

    int warp = threadIdx.x >> 5;
    int lane = threadIdx.x & 31;
    int r0 = (blockIdx.x * 8 + warp) * 4;
    if (r0 >= n) return;
    int rl = min(r0 + 3, n - 1);

    const float* xr0 = x + (size_t)r0 * IN_F;
    const float* xr1 = x + (size_t)min(r0 + 1, rl) * IN_F;
    const float* xr2 = x + (size_t)min(r0 + 2, rl) * IN_F;
    const float* xr3 = x + (size_t)rl * IN_F;

    float4 z = make_float4(0.f, 0.f, 0.f, 0.f);
    float4 a0_0=z, a0_1=z, a0_2=z, a0_3=z;
    float4 a1_0=z, a1_1=z, a1_2=z, a1_3=z;
    float4 a2_0=z, a2_1=z, a2_2=z, a2_3=z;
    float4 a3_0=z, a3_1=z, a3_2=z, a3_3=z;

#pragma unroll 4
    for (int i = 0; i < IN_F / 32; i++) {
        int k = lane + (i << 5);
        float x0 = xr0[k], x1 = xr1[k], x2 = xr2[k], x3 = xr3[k];
#define GSTEP(c) { \
        float w0 = w_s[(4*(c)+0)*IN_F + k]; \
        float w1 = w_s[(4*(c)+1)*IN_F + k]; \
        float w2 = w_s[(4*(c)+2)*IN_F + k]; \
        float w3 = w_s[(4*(c)+3)*IN_F + k]; \
        a0_##c.x += x0*w0; a0_##c.y += x0*w1; a0_##c.z += x0*w2; a0_##c.w += x0*w3; \
        a1_##c.x += x1*w0; a1_##c.y += x1*w1; a1_##c.z += x1*w2; a1_##c.w += x1*w3; \
        a2_##c.x += x2*w0; a2_##c.y += x2*w1; a2_##c.z += x2*w2; a2_##c.w += x2*w3; \
        a3_##c.x += x3*w0; a3_##c.y += x3*w1; a3_##c.z += x3*w2; a3_##c.w += x3*w3; }
        GSTEP(0) GSTEP(1) GSTEP(2) GSTEP(3)
#undef GSTEP
    }

#define RED(v) { v.x += __shfl_xor_sync(0xffffffffu, v.x, off); \
                 v.y += __shfl_xor_sync(0xffffffffu, v.y, off); \
                 v.z += __shfl_xor_sync(0xffffffffu, v.z, off); \
                 v.w += __shfl_xor_sync(0xffffffffu, v.w, off); }
#pragma unroll
    for (int off = 16; off; off >>= 1) {
        RED(a0_0) RED(a0_1) RED(a0_2) RED(a0_3)
        RED(a1_0) RED(a1_1) RED(a1_2) RED(a1_3)
        RED(a2_0) RED(a2_1) RED(a2_2) RED(a2_3)
        RED(a3_0) RED(a3_1) RED(a3_2) RED(a3_3)
    }
#undef RED

    if (lane == 0) store_row1(r0 + 0, n, a0_0, a0_1, a0_2, a0_3);
    if (lane == 1) store_row1(r0 + 1, n, a1_0, a1_1, a1_2, a1_3);
    if (lane == 2) store_row1(r0 + 2, n, a2_0, a2_1, a2_2, a2_3);
    if (lane == 3) store_row1(r0 + 3, n, a3_0, a3_1, a3_2, a3_3);
}

// ---------------- CSR gather: agg[i] = dis[i]*(sum_{s in N(i)} hs[s] + hs[i]) -
__device__ __forceinline__ void acc_row(int s, float4& v0, float4& v1,
                                        float4& v2, float4& v3) {
    const float4* hp = (const float4*)(g_hbuf + (size_t)s * HID);
    float4 t0 = hp[0], t1 = hp[1], t2 = hp[2], t3 = hp[3];
    v0.x += t0.x; v0.y += t0.y; v0.z += t0.z; v0.w += t0.w;
    v1.x += t1.x; v1.y += t1.y; v1.z += t1.z; v1.w += t1.w;
    v2.x += t2.x; v2.y += t2.y; v2.z += t2.z; v2.w += t2.w;
    v3.x += t3.x; v3.y += t3.y; v3.z += t3.z; v3.w += t3.w;
}

__global__ void gather_kernel(float* __restrict__ agg, int n) {
    int i = blockIdx.x * blockDim.x + threadIdx.x;
    if (i >= n) return;

    unsigned packed = g_rowptr[i];
    int end   = (int)(packed & RP_MASK);
    int nlow  = (int)(packed >> 22);
    int start = (i > 0) ? (int)(g_rowptr[i - 1] & RP_MASK) : 0;
    int mid   = start + nlow;
    int deg   = end - start;
    float dis = rsqrtf((float)deg + 1.0f);

    const float4* selfp = (const float4*)(g_hbuf + (size_t)i * HID);
    float4 v0 = selfp[0], v1 = selfp[1], v2 = selfp[2], v3 = selfp[3];  // self loop

    for (int j = start; j < mid; j++)
        acc_row((int)g_csr_lo[j], v0, v1, v2, v3);
    for (int j = mid; j < end; j++)
        acc_row((int)g_csr_lo[j] | 0x10000, v0, v1, v2, v3);

    float4* ap = (float4*)(agg + (size_t)i * HID);
    ap[0] = make_float4(dis*v0.x, dis*v0.y, dis*v0.z, dis*v0.w);
    ap[1] = make_float4(dis*v1.x, dis*v1.y, dis*v1.z, dis*v1.w);
    ap[2] = make_float4(dis*v2.x, dis*v2.y, dis*v2.z, dis*v2.w);
    ap[3] = make_float4(dis*v3.x, dis*v3.y, dis*v3.z, dis*v3.w);
}

// ---------------- layer 2: hbuf = hs2 = dis * (relu(agg1+b1) @ W2) -----------
__global__ void layer2_kernel(const float* __restrict__ b1,
                              const float* __restrict__ W2,
                              const float* __restrict__ agg, int n)
{
    __shared__ float W2s[HID * HID];
    __shared__ float b1s[HID];
    if (threadIdx.x < HID * HID) W2s[threadIdx.x] = W2[threadIdx.x];
    if (threadIdx.x < HID)       b1s[threadIdx.x] = b1[threadIdx.x];
    __syncthreads();

    int i = blockIdx.x * blockDim.x + threadIdx.x;
    if (i >= n) return;

    const float4* ap = (const float4*)(agg + (size_t)i * HID);
    float4 v0 = ap[0], v1 = ap[1], v2 = ap[2], v3 = ap[3];
    v0.x = fmaxf(v0.x + b1s[0],  0.f); v0.y = fmaxf(v0.y + b1s[1],  0.f);
    v0.z = fmaxf(v0.z + b1s[2],  0.f); v0.w = fmaxf(v0.w + b1s[3],  0.f);
    v1.x = fmaxf(v1.x + b1s[4],  0.f); v1.y = fmaxf(v1.y + b1s[5],  0.f);
    v1.z = fmaxf(v1.z + b1s[6],  0.f); v1.w = fmaxf(v1.w + b1s[7],  0.f);
    v2.x = fmaxf(v2.x + b1s[8],  0.f); v2.y = fmaxf(v2.y + b1s[9],  0.f);
    v2.z = fmaxf(v2.z + b1s[10], 0.f); v2.w = fmaxf(v2.w + b1s[11], 0.f);
    v3.x = fmaxf(v3.x + b1s[12], 0.f); v3.y = fmaxf(v3.y + b1s[13], 0.f);
    v3.z = fmaxf(v3.z + b1s[14], 0.f); v3.w = fmaxf(v3.w + b1s[15], 0.f);

#define DOT(J) ( v0.x*W2s[ 0*HID+(J)] + v0.y*W2s[ 1*HID+(J)] + v0.z*W2s[ 2*HID+(J)] + v0.w*W2s[ 3*HID+(J)] \
               + v1.x*W2s[ 4*HID+(J)] + v1.y*W2s[ 5*HID+(J)] + v1.z*W2s[ 6*HID+(J)] + v1.w*W2s[ 7*HID+(J)] \
               + v2.x*W2s[ 8*HID+(J)] + v2.y*W2s[ 9*HID+(J)] + v2.z*W2s[10*HID+(J)] + v2.w*W2s[11*HID+(J)] \
               + v3.x*W2s[12*HID+(J)] + v3.y*W2s[13*HID+(J)] + v3.z*W2s[14*HID+(J)] + v3.w*W2s[15*HID+(J)] )
    float4 s0 = make_float4(DOT(0),  DOT(1),  DOT(2),  DOT(3));
    float4 s1 = make_float4(DOT(4),  DOT(5),  DOT(6),  DOT(7));
    float4 s2 = make_float4(DOT(8),  DOT(9),  DOT(10), DOT(11));
    float4 s3 = make_float4(DOT(12), DOT(13), DOT(14), DOT(15));
#undef DOT

    float d = node_dis(i);
    float4* hp = (float4*)(g_hbuf + (size_t)i * HID);
    hp[0] = make_float4(d*s0.x, d*s0.y, d*s0.z, d*s0.w);
    hp[1] = make_float4(d*s1.x, d*s1.y, d*s1.z, d*s1.w);
    hp[2] = make_float4(d*s2.x, d*s2.y, d*s2.z, d*s2.w);
    hp[3] = make_float4(d*s3.x, d*s3.y, d*s3.z, d*s3.w);
}

// ---------------- final: out = log_softmax(out + b2)  (in place) -------------
__global__ void final_kernel(const float* __restrict__ b2,
                             float* __restrict__ out, int n)
{
    __shared__ float b2s[HID];
    if (threadIdx.x < HID) b2s[threadIdx.x] = b2[threadIdx.x];
    __syncthreads();

    int i = blockIdx.x * blockDim.x + threadIdx.x;
    if (i >= n) return;

    float4* op = (float4*)(out + (size_t)i * HID);
    float4 v0 = op[0], v1 = op[1], v2 = op[2], v3 = op[3];
    v0.x += b2s[0];  v0.y += b2s[1];  v0.z += b2s[2];  v0.w += b2s[3];
    v1.x += b2s[4];  v1.y += b2s[5];  v1.z += b2s[6];  v1.w += b2s[7];
    v2.x += b2s[8];  v2.y += b2s[9];  v2.z += b2s[10]; v2.w += b2s[11];
    v3.x += b2s[12]; v3.y += b2s[13]; v3.z += b2s[14]; v3.w += b2s[15];

    float m = fmaxf(fmaxf(fmaxf(v0.x, v0.y), fmaxf(v0.z, v0.w)),
             fmaxf(fmaxf(fmaxf(v1.x, v1.y), fmaxf(v1.z, v1.w)),
             fmaxf(fmaxf(fmaxf(v2.x, v2.y), fmaxf(v2.z, v2.w)),
                   fmaxf(fmaxf(v3.x, v3.y), fmaxf(v3.z, v3.w)))));

    float ssum = expf(v0.x - m) + expf(v0.y - m) + expf(v0.z - m) + expf(v0.w - m)
               + expf(v1.x - m) + expf(v1.y - m) + expf(v1.z - m) + expf(v1.w - m)
               + expf(v2.x - m) + expf(v2.y - m) + expf(v2.z - m) + expf(v2.w - m)
               + expf(v3.x - m) + expf(v3.y - m) + expf(v3.z - m) + expf(v3.w - m);
    float lse = m + logf(ssum);

    op[0] = make_float4(v0.x - lse, v0.y - lse, v0.z - lse, v0.w - lse);
    op[1] = make_float4(v1.x - lse, v1.y - lse, v1.z - lse, v1.w - lse);
    op[2] = make_float4(v2.x - lse, v2.y - lse, v2.z - lse, v2.w - lse);
    op[3] = make_float4(v3.x - lse, v3.y - lse, v3.z - lse, v3.w - lse);
}

// ---------------- launch ------------------------------------------------------
extern "C" void kernel_launch(void* const* d_in, const int* in_sizes, int n_in,
                              void* d_out, int out_size)
{
    const float* x  = nullptr;
    const void*  ei = nullptr;
    const float* W1 = nullptr;
    const float* W2 = nullptr;
    const float* b1 = nullptr;
    const float* b2 = nullptr;
    long long x_elems = 0, ei_elems = 0;

    for (int i = 0; i < n_in; i++) {
        int sz = in_sizes[i];
        if (sz >= 10000000) {                 // x (51.2M f32)
            x = (const float*)d_in[i]; x_elems = sz;
        } else if (sz >= 1000000) {           // edge_index (6.4M elems, dtype probed)
            ei = d_in[i]; ei_elems = sz;
        } else if (sz == IN_F * HID) {        // W1
            W1 = (const float*)d_in[i];
        } else if (sz == HID * HID) {         // W2
            W2 = (const float*)d_in[i];
        } else if (sz == HID) {               // b1 then b2
            if (!b1) b1 = (const float*)d_in[i];
            else     b2 = (const float*)d_in[i];
        }
    }
    if (!b2) b2 = b1;
    float* out = (float*)d_out;
    int*   sc  = (int*)d_out;                 // build-time scratch (consumed pre-gather1)

    int N = (int)(x_elems / IN_F);            // 100000
    int E = (int)(ei_elems / 2);              // 3200000
    if (E > E_MAX) E = E_MAX;

    int nb_nodes = (N + 255) / 256;
    int nb_edges = (E + 255) / 256;
    int nb_gemm  = (N + 31) / 32;
    int nb_zero  = (2 * N + 255) / 256;

    detect_ei_kernel   <<<1, 32>>>((const int*)ei);

    // CSR build (scratch in d_out; reused by both gathers)
    zero_scratch_kernel<<<nb_zero, 256>>>(sc, 2 * N);
    hist_kernel        <<<nb_edges, 256>>>(ei, sc, E, N);
    scan_block_kernel  <<<nb_nodes, 256>>>(sc, N);
    scan_bsum_kernel   <<<1, 512>>>(nb_nodes);
    finalize_kernel    <<<nb_nodes, 256>>>(sc, N);
    fill_kernel        <<<nb_edges, 256>>>(ei, sc, E, N);

    // layer 1: hs1 -> hbuf, agg1 -> d_out (overwrites scratch)
    gemm1_kernel       <<<nb_gemm, 256>>>(x, W1, N);
    gather_kernel      <<<nb_nodes, 256>>>(out, N);

    // layer 2: hs2 -> hbuf (overwrite), agg2 -> d_out (overwrite)
    layer2_kernel      <<<nb_nodes, 256>>>(b1, W2, out, N);
    gather_kernel      <<<nb_nodes, 256>>>(out, N);

    final_kernel       <<<nb_nodes, 256>>>(b2, out, N);
}

// round 11
// speedup vs baseline: 1.3664x; 1.1735x over previous
#include <cuda_runtime.h>
#include <cuda_bf16.h>

#define N_NODES 100000
#define E_MAX   3200000
#define IN_F    512
#define HID     16
#define RP_MASK 0x3FFFFFu

// ---------------- scratch: 13.2 MB total statics (== proven-pass R7/R10) ----
__device__ __align__(16) unsigned short g_csr_lo[E_MAX];          // 6.4 MB
__device__ __align__(16) float          g_hbuf  [N_NODES * HID];  // 6.4 MB
__device__ unsigned int g_rowptr[N_NODES];                        // 0.4 MB: end | (nlow<<22)
__device__ int g_bsum[512];
__device__ int g_ei64;

// ---------------- helpers ---------------------------------------------------
__device__ __forceinline__ int load_idx(const void* ei, size_t elem, int is64) {
    if (is64) return (int)((const long long*)ei)[elem];
    return ((const int*)ei)[elem];
}

__device__ __forceinline__ float node_dis(int i) {
    unsigned end = g_rowptr[i] & RP_MASK;
    unsigned st  = (i > 0) ? (g_rowptr[i - 1] & RP_MASK) : 0u;
    return rsqrtf((float)(end - st) + 1.0f);   // +1 = self loop
}

// ---------------- edge-index dtype probe -------------------------------------
__global__ void detect_ei_kernel(const int* __restrict__ ei32) {
    int nz = 0;
    for (int i = threadIdx.x; i < 256; i += 32)
        if (ei32[2 * i + 1] != 0) nz = 1;
    nz = __any_sync(0xffffffffu, nz);
    if (threadIdx.x == 0) g_ei64 = nz ? 0 : 1;
}

// ---------------- CSR build (cursors/counts live in d_out scratch) -----------
// scratch layout (ints): [0,n)=cnt_total  [n,2n)=cnt_low  [2n,3n)=cur_low  [3n,4n)=cur_high
__global__ void zero_scratch_kernel(int* __restrict__ sc, int n2) {
    int i = blockIdx.x * blockDim.x + threadIdx.x;
    if (i < n2) sc[i] = 0;
}

__global__ void hist_kernel(const void* __restrict__ ei, int* __restrict__ sc,
                            int E, int n) {
    int e = blockIdx.x * blockDim.x + threadIdx.x;
    if (e >= E) return;
    int is64 = g_ei64;
    int s = load_idx(ei, (size_t)e, is64);
    int d = load_idx(ei, (size_t)E + e, is64);
    if ((unsigned)s >= (unsigned)n) return;
    if ((unsigned)d >= (unsigned)n) return;
    atomicAdd(&sc[d], 1);
    if (s < 65536) atomicAdd(&sc[n + d], 1);
}

// block-local exclusive scan of cnt_total -> cur_low slot; block sums -> g_bsum
__global__ __launch_bounds__(256) void scan_block_kernel(int* __restrict__ sc, int n) {
    __shared__ int s[256];
    int i = blockIdx.x * 256 + threadIdx.x;
    int v = (i < n) ? sc[i] : 0;
    s[threadIdx.x] = v;
    __syncthreads();
#pragma unroll
    for (int off = 1; off < 256; off <<= 1) {
        int t = (threadIdx.x >= off) ? s[threadIdx.x - off] : 0;
        __syncthreads();
        s[threadIdx.x] += t;
        __syncthreads();
    }
    if (i < n) sc[2 * n + i] = s[threadIdx.x] - v;
    if (threadIdx.x == 255) g_bsum[blockIdx.x] = s[255];
}

__global__ __launch_bounds__(512) void scan_bsum_kernel(int nb) {
    __shared__ int s[512];
    int v = (threadIdx.x < nb) ? g_bsum[threadIdx.x] : 0;
    s[threadIdx.x] = v;
    __syncthreads();
#pragma unroll
    for (int off = 1; off < 512; off <<= 1) {
        int t = (threadIdx.x >= off) ? s[threadIdx.x - off] : 0;
        __syncthreads();
        s[threadIdx.x] += t;
        __syncthreads();
    }
    if (threadIdx.x < nb) g_bsum[threadIdx.x] = s[threadIdx.x] - v;
}

// finalize: cursors + packed rowptr (end | nlow<<22)
__global__ void finalize_kernel(int* __restrict__ sc, int n) {
    int i = blockIdx.x * blockDim.x + threadIdx.x;
    if (i >= n) return;
    int start = sc[2 * n + i] + g_bsum[i >> 8];
    int deg   = sc[i];
    int nlow  = sc[n + i];
    sc[2 * n + i] = start;               // cur_low
    sc[3 * n + i] = start + nlow;        // cur_high
    g_rowptr[i] = (unsigned)(start + deg) | ((unsigned)nlow << 22);
}

__global__ void fill_kernel(const void* __restrict__ ei, int* __restrict__ sc,
                            int E, int n) {
    int e = blockIdx.x * blockDim.x + threadIdx.x;
    if (e >= E) return;
    int is64 = g_ei64;
    int s = load_idx(ei, (size_t)e, is64);
    int d = load_idx(ei, (size_t)E + e, is64);
    if ((unsigned)s >= (unsigned)n) return;
    if ((unsigned)d >= (unsigned)n) return;
    int pos = (s < 65536) ? atomicAdd(&sc[2 * n + d], 1)
                          : atomicAdd(&sc[3 * n + d], 1);
    if ((unsigned)pos < (unsigned)E_MAX)
        g_csr_lo[pos] = (unsigned short)(s & 0xFFFF);
}

// ---------------- GEMM1: hbuf = hs1 = dis * (x @ W1) -------------------------
__device__ __forceinline__ void store_row1(int r, int n,
                                           float4 b0, float4 b1, float4 b2, float4 b3) {
    if (r >= n) return;
    float d = node_dis(r);
    float4* hp = (float4*)(g_hbuf + (size_t)r * HID);
    hp[0] = make_float4(d*b0.x, d*b0.y, d*b0.z, d*b0.w);
    hp[1] = make_float4(d*b1.x, d*b1.y, d*b1.z, d*b1.w);
    hp[2] = make_float4(d*b2.x, d*b2.y, d*b2.z, d*b2.w);
    hp[3] = make_float4(d*b3.x, d*b3.y, d*b3.z, d*b3.w);
}

__global__ __launch_bounds__(256) void gemm1_kernel(
    const float* __restrict__ x, const float* __restrict__ W1, int n)
{
    __shared__ float w_s[HID * IN_F];
    for (int idx = threadIdx.x; idx < IN_F * HID; idx += blockDim.x) {
        int k = idx >> 4, j = idx & 15;
        w_s[j * IN_F + k] = W1[idx];
    }
    __syncthreads();

    int warp = threadIdx.x >> 5;
    int lane = threadIdx.x & 31;
    int r0 = (blockIdx.x * 8 + warp) * 4;
    if (r0 >= n) return;
    int rl = min(r0 + 3, n - 1);

    const float* xr0 = x + (size_t)r0 * IN_F;
    const float* xr1 = x + (size_t)min(r0 + 1, rl) * IN_F;
    const float* xr2 = x + (size_t)min(r0 + 2, rl) * IN_F;
    const float* xr3 = x + (size_t)rl * IN_F;

    float4 z = make_float4(0.f, 0.f, 0.f, 0.f);
    float4 a0_0=z, a0_1=z, a0_2=z, a0_3=z;
    float4 a1_0=z, a1_1=z, a1_2=z, a1_3=z;
    float4 a2_0=z, a2_1=z, a2_2=z, a2_3=z;
    float4 a3_0=z, a3_1=z, a3_2=z, a3_3=z;

#pragma unroll 4
    for (int i = 0; i < IN_F / 32; i++) {
        int k = lane + (i << 5);
        float x0 = xr0[k], x1 = xr1[k], x2 = xr2[k], x3 = xr3[k];
#define GSTEP(c) { \
        float w0 = w_s[(4*(c)+0)*IN_F + k]; \
        float w1 = w_s[(4*(c)+1)*IN_F + k]; \
        float w2 = w_s[(4*(c)+2)*IN_F + k]; \
        float w3 = w_s[(4*(c)+3)*IN_F + k]; \
        a0_##c.x += x0*w0; a0_##c.y += x0*w1; a0_##c.z += x0*w2; a0_##c.w += x0*w3; \
        a1_##c.x += x1*w0; a1_##c.y += x1*w1; a1_##c.z += x1*w2; a1_##c.w += x1*w3; \
        a2_##c.x += x2*w0; a2_##c.y += x2*w1; a2_##c.z += x2*w2; a2_##c.w += x2*w3; \
        a3_##c.x += x3*w0; a3_##c.y += x3*w1; a3_##c.z += x3*w2; a3_##c.w += x3*w3; }
        GSTEP(0) GSTEP(1) GSTEP(2) GSTEP(3)
#undef GSTEP
    }

#define RED(v) { v.x += __shfl_xor_sync(0xffffffffu, v.x, off); \
                 v.y += __shfl_xor_sync(0xffffffffu, v.y, off); \
                 v.z += __shfl_xor_sync(0xffffffffu, v.z, off); \
                 v.w += __shfl_xor_sync(0xffffffffu, v.w, off); }
#pragma unroll
    for (int off = 16; off; off >>= 1) {
        RED(a0_0) RED(a0_1) RED(a0_2) RED(a0_3)
        RED(a1_0) RED(a1_1) RED(a1_2) RED(a1_3)
        RED(a2_0) RED(a2_1) RED(a2_2) RED(a2_3)
        RED(a3_0) RED(a3_1) RED(a3_2) RED(a3_3)
    }
#undef RED

    if (lane == 0) store_row1(r0 + 0, n, a0_0, a0_1, a0_2, a0_3);
    if (lane == 1) store_row1(r0 + 1, n, a1_0, a1_1, a1_2, a1_3);
    if (lane == 2) store_row1(r0 + 2, n, a2_0, a2_1, a2_2, a2_3);
    if (lane == 3) store_row1(r0 + 3, n, a3_0, a3_1, a3_2, a3_3);
}

// ---------------- quad-per-node CSR gather ------------------------------------
// 4 lanes handle one node; lane q owns float4 #q of the row. Neighbor row loads
// are 4x16B contiguous per quad -> coalesced 64B; ~4x fewer L1tex wavefronts
// than thread-per-node, and 8 nodes/warp smooths degree imbalance.
__global__ __launch_bounds__(256) void gather_kernel(float* __restrict__ agg, int n) {
    int t = blockIdx.x * blockDim.x + threadIdx.x;
    int i = t >> 2;
    int q = t & 3;
    if (i >= n) return;

    unsigned packed = g_rowptr[i];
    int end   = (int)(packed & RP_MASK);
    int nlow  = (int)(packed >> 22);
    int start = (i > 0) ? (int)(g_rowptr[i - 1] & RP_MASK) : 0;
    int mid   = start + nlow;
    float dis = rsqrtf((float)(end - start) + 1.0f);

    // self loop
    float4 v = ((const float4*)(g_hbuf + (size_t)i * HID))[q];

    for (int j = start; j < mid; j++) {
        int s = (int)g_csr_lo[j];
        float4 tv = ((const float4*)(g_hbuf + (size_t)s * HID))[q];
        v.x += tv.x; v.y += tv.y; v.z += tv.z; v.w += tv.w;
    }
    for (int j = mid; j < end; j++) {
        int s = (int)g_csr_lo[j] | 0x10000;
        float4 tv = ((const float4*)(g_hbuf + (size_t)s * HID))[q];
        v.x += tv.x; v.y += tv.y; v.z += tv.z; v.w += tv.w;
    }

    ((float4*)(agg + (size_t)i * HID))[q] =
        make_float4(dis*v.x, dis*v.y, dis*v.z, dis*v.w);
}

// ---------------- layer 2: hbuf = hs2 = dis * (relu(agg1+b1) @ W2) -----------
__global__ void layer2_kernel(const float* __restrict__ b1,
                              const float* __restrict__ W2,
                              const float* __restrict__ agg, int n)
{
    __shared__ float W2s[HID * HID];
    __shared__ float b1s[HID];
    if (threadIdx.x < HID * HID) W2s[threadIdx.x] = W2[threadIdx.x];
    if (threadIdx.x < HID)       b1s[threadIdx.x] = b1[threadIdx.x];
    __syncthreads();

    int i = blockIdx.x * blockDim.x + threadIdx.x;
    if (i >= n) return;

    const float4* ap = (const float4*)(agg + (size_t)i * HID);
    float4 v0 = ap[0], v1 = ap[1], v2 = ap[2], v3 = ap[3];
    v0.x = fmaxf(v0.x + b1s[0],  0.f); v0.y = fmaxf(v0.y + b1s[1],  0.f);
    v0.z = fmaxf(v0.z + b1s[2],  0.f); v0.w = fmaxf(v0.w + b1s[3],  0.f);
    v1.x = fmaxf(v1.x + b1s[4],  0.f); v1.y = fmaxf(v1.y + b1s[5],  0.f);
    v1.z = fmaxf(v1.z + b1s[6],  0.f); v1.w = fmaxf(v1.w + b1s[7],  0.f);
    v2.x = fmaxf(v2.x + b1s[8],  0.f); v2.y = fmaxf(v2.y + b1s[9],  0.f);
    v2.z = fmaxf(v2.z + b1s[10], 0.f); v2.w = fmaxf(v2.w + b1s[11], 0.f);
    v3.x = fmaxf(v3.x + b1s[12], 0.f); v3.y = fmaxf(v3.y + b1s[13], 0.f);
    v3.z = fmaxf(v3.z + b1s[14], 0.f); v3.w = fmaxf(v3.w + b1s[15], 0.f);

#define DOT(J) ( v0.x*W2s[ 0*HID+(J)] + v0.y*W2s[ 1*HID+(J)] + v0.z*W2s[ 2*HID+(J)] + v0.w*W2s[ 3*HID+(J)] \
               + v1.x*W2s[ 4*HID+(J)] + v1.y*W2s[ 5*HID+(J)] + v1.z*W2s[ 6*HID+(J)] + v1.w*W2s[ 7*HID+(J)] \
               + v2.x*W2s[ 8*HID+(J)] + v2.y*W2s[ 9*HID+(J)] + v2.z*W2s[10*HID+(J)] + v2.w*W2s[11*HID+(J)] \
               + v3.x*W2s[12*HID+(J)] + v3.y*W2s[13*HID+(J)] + v3.z*W2s[14*HID+(J)] + v3.w*W2s[15*HID+(J)] )
    float4 s0 = make_float4(DOT(0),  DOT(1),  DOT(2),  DOT(3));
    float4 s1 = make_float4(DOT(4),  DOT(5),  DOT(6),  DOT(7));
    float4 s2 = make_float4(DOT(8),  DOT(9),  DOT(10), DOT(11));
    float4 s3 = make_float4(DOT(12), DOT(13), DOT(14), DOT(15));
#undef DOT

    float d = node_dis(i);
    float4* hp = (float4*)(g_hbuf + (size_t)i * HID);
    hp[0] = make_float4(d*s0.x, d*s0.y, d*s0.z, d*s0.w);
    hp[1] = make_float4(d*s1.x, d*s1.y, d*s1.z, d*s1.w);
    hp[2] = make_float4(d*s2.x, d*s2.y, d*s2.z, d*s2.w);
    hp[3] = make_float4(d*s3.x, d*s3.y, d*s3.z, d*s3.w);
}

// ---------------- final: out = log_softmax(out + b2)  (in place) -------------
__global__ void final_kernel(const float* __restrict__ b2,
                             float* __restrict__ out, int n)
{
    __shared__ float b2s[HID];
    if (threadIdx.x < HID) b2s[threadIdx.x] = b2[threadIdx.x];
    __syncthreads();

    int i = blockIdx.x * blockDim.x + threadIdx.x;
    if (i >= n) return;

    float4* op = (float4*)(out + (size_t)i * HID);
    float4 v0 = op[0], v1 = op[1], v2 = op[2], v3 = op[3];
    v0.x += b2s[0];  v0.y += b2s[1];  v0.z += b2s[2];  v0.w += b2s[3];
    v1.x += b2s[4];  v1.y += b2s[5];  v1.z += b2s[6];  v1.w += b2s[7];
    v2.x += b2s[8];  v2.y += b2s[9];  v2.z += b2s[10]; v2.w += b2s[11];
    v3.x += b2s[12]; v3.y += b2s[13]; v3.z += b2s[14]; v3.w += b2s[15];

    float m = fmaxf(fmaxf(fmaxf(v0.x, v0.y), fmaxf(v0.z, v0.w)),
             fmaxf(fmaxf(fmaxf(v1.x, v1.y), fmaxf(v1.z, v1.w)),
             fmaxf(fmaxf(fmaxf(v2.x, v2.y), fmaxf(v2.z, v2.w)),
                   fmaxf(fmaxf(v3.x, v3.y), fmaxf(v3.z, v3.w)))));

    float ssum = expf(v0.x - m) + expf(v0.y - m) + expf(v0.z - m) + expf(v0.w - m)
               + expf(v1.x - m) + expf(v1.y - m) + expf(v1.z - m) + expf(v1.w - m)
               + expf(v2.x - m) + expf(v2.y - m) + expf(v2.z - m) + expf(v2.w - m)
               + expf(v3.x - m) + expf(v3.y - m) + expf(v3.z - m) + expf(v3.w - m);
    float lse = m + logf(ssum);

    op[0] = make_float4(v0.x - lse, v0.y - lse, v0.z - lse, v0.w - lse);
    op[1] = make_float4(v1.x - lse, v1.y - lse, v1.z - lse, v1.w - lse);
    op[2] = make_float4(v2.x - lse, v2.y - lse, v2.z - lse, v2.w - lse);
    op[3] = make_float4(v3.x - lse, v3.y - lse, v3.z - lse, v3.w - lse);
}

// ---------------- launch ------------------------------------------------------
extern "C" void kernel_launch(void* const* d_in, const int* in_sizes, int n_in,
                              void* d_out, int out_size)
{
    const float* x  = nullptr;
    const void*  ei = nullptr;
    const float* W1 = nullptr;
    const float* W2 = nullptr;
    const float* b1 = nullptr;
    const float* b2 = nullptr;
    long long x_elems = 0, ei_elems = 0;

    for (int i = 0; i < n_in; i++) {
        int sz = in_sizes[i];
        if (sz >= 10000000) {                 // x (51.2M f32)
            x = (const float*)d_in[i]; x_elems = sz;
        } else if (sz >= 1000000) {           // edge_index (6.4M elems, dtype probed)
            ei = d_in[i]; ei_elems = sz;
        } else if (sz == IN_F * HID) {        // W1
            W1 = (const float*)d_in[i];
        } else if (sz == HID * HID) {         // W2
            W2 = (const float*)d_in[i];
        } else if (sz == HID) {               // b1 then b2
            if (!b1) b1 = (const float*)d_in[i];
            else     b2 = (const float*)d_in[i];
        }
    }
    if (!b2) b2 = b1;
    float* out = (float*)d_out;
    int*   sc  = (int*)d_out;                 // build-time scratch (consumed pre-gather1)

    int N = (int)(x_elems / IN_F);            // 100000
    int E = (int)(ei_elems / 2);              // 3200000
    if (E > E_MAX) E = E_MAX;

    int nb_nodes  = (N + 255) / 256;
    int nb_edges  = (E + 255) / 256;
    int nb_gemm   = (N + 31) / 32;
    int nb_zero   = (2 * N + 255) / 256;
    int nb_gather = (4 * N + 255) / 256;      // quad per node

    detect_ei_kernel   <<<1, 32>>>((const int*)ei);

    // CSR build (scratch in d_out; reused by both gathers)
    zero_scratch_kernel<<<nb_zero, 256>>>(sc, 2 * N);
    hist_kernel        <<<nb_edges, 256>>>(ei, sc, E, N);
    scan_block_kernel  <<<nb_nodes, 256>>>(sc, N);
    scan_bsum_kernel   <<<1, 512>>>(nb_nodes);
    finalize_kernel    <<<nb_nodes, 256>>>(sc, N);
    fill_kernel        <<<nb_edges, 256>>>(ei, sc, E, N);

    // layer 1: hs1 -> hbuf, agg1 -> d_out (overwrites scratch)
    gemm1_kernel       <<<nb_gemm, 256>>>(x, W1, N);
    gather_kernel      <<<nb_gather, 256>>>(out, N);

    // layer 2: hs2 -> hbuf (overwrite), agg2 -> d_out (overwrite)
    layer2_kernel      <<<nb_nodes, 256>>>(b1, W2, out, N);
    gather_kernel      <<<nb_gather, 256>>>(out, N);

    final_kernel       <<<nb_nodes, 256>>>(b2, out, N);
}

// round 14
// speedup vs baseline: 1.8486x; 1.3530x over previous
#include <cuda_runtime.h>
#include <cuda_bf16.h>

#define N_NODES 100000
#define E_MAX   3200000
#define IN_F    512
#define HID     16
#define RP_MASK 0x3FFFFFu

// ---------------- scratch: 13.2 MB total statics (proven-pass budget) -------
__device__ __align__(16) unsigned short g_csr_lo[E_MAX];          // 6.4 MB
__device__ __align__(16) float          g_hbuf  [N_NODES * HID];  // 6.4 MB
__device__ unsigned int g_rowptr[N_NODES];                        // 0.4 MB: end | (nlow<<22)
__device__ int g_bsum[512];
__device__ int g_ei64;

// ---------------- helpers ---------------------------------------------------
__device__ __forceinline__ int load_idx(const void* ei, size_t elem, int is64) {
    if (is64) return (int)((const long long*)ei)[elem];
    return ((const int*)ei)[elem];
}

__device__ __forceinline__ float node_dis(int i) {
    unsigned end = g_rowptr[i] & RP_MASK;
    unsigned st  = (i > 0) ? (g_rowptr[i - 1] & RP_MASK) : 0u;
    return rsqrtf((float)(end - st) + 1.0f);   // +1 = self loop
}

// ---------------- edge-index dtype probe -------------------------------------
__global__ void detect_ei_kernel(const int* __restrict__ ei32) {
    int nz = 0;
    for (int i = threadIdx.x; i < 256; i += 32)
        if (ei32[2 * i + 1] != 0) nz = 1;
    nz = __any_sync(0xffffffffu, nz);
    if (threadIdx.x == 0) g_ei64 = nz ? 0 : 1;
}

// ---------------- CSR build (cursors/counts live in d_out scratch) -----------
// scratch ints: [0,n)=cnt_total [n,2n)=cnt_low [2n,3n)=cur_low [3n,4n)=cur_high
__global__ void zero_scratch_kernel(int* __restrict__ sc, int n2) {
    int i = blockIdx.x * blockDim.x + threadIdx.x;
    if (i < n2) sc[i] = 0;
}

__global__ void hist_kernel(const void* __restrict__ ei, int* __restrict__ sc,
                            int E, int n) {
    int e = blockIdx.x * blockDim.x + threadIdx.x;
    if (e >= E) return;
    int is64 = g_ei64;
    int s = load_idx(ei, (size_t)e, is64);
    int d = load_idx(ei, (size_t)E + e, is64);
    if ((unsigned)s >= (unsigned)n) return;
    if ((unsigned)d >= (unsigned)n) return;
    atomicAdd(&sc[d], 1);
    if (s < 65536) atomicAdd(&sc[n + d], 1);
}

__global__ __launch_bounds__(256) void scan_block_kernel(int* __restrict__ sc, int n) {
    __shared__ int s[256];
    int i = blockIdx.x * 256 + threadIdx.x;
    int v = (i < n) ? sc[i] : 0;
    s[threadIdx.x] = v;
    __syncthreads();
#pragma unroll
    for (int off = 1; off < 256; off <<= 1) {
        int t = (threadIdx.x >= off) ? s[threadIdx.x - off] : 0;
        __syncthreads();
        s[threadIdx.x] += t;
        __syncthreads();
    }
    if (i < n) sc[2 * n + i] = s[threadIdx.x] - v;
    if (threadIdx.x == 255) g_bsum[blockIdx.x] = s[255];
}

__global__ __launch_bounds__(512) void scan_bsum_kernel(int nb) {
    __shared__ int s[512];
    int v = (threadIdx.x < nb) ? g_bsum[threadIdx.x] : 0;
    s[threadIdx.x] = v;
    __syncthreads();
#pragma unroll
    for (int off = 1; off < 512; off <<= 1) {
        int t = (threadIdx.x >= off) ? s[threadIdx.x - off] : 0;
        __syncthreads();
        s[threadIdx.x] += t;
        __syncthreads();
    }
    if (threadIdx.x < nb) g_bsum[threadIdx.x] = s[threadIdx.x] - v;
}

__global__ void finalize_kernel(int* __restrict__ sc, int n) {
    int i = blockIdx.x * blockDim.x + threadIdx.x;
    if (i >= n) return;
    int start = sc[2 * n + i] + g_bsum[i >> 8];
    int deg   = sc[i];
    int nlow  = sc[n + i];
    sc[2 * n + i] = start;               // cur_low
    sc[3 * n + i] = start + nlow;        // cur_high
    g_rowptr[i] = (unsigned)(start + deg) | ((unsigned)nlow << 22);
}

__global__ void fill_kernel(const void* __restrict__ ei, int* __restrict__ sc,
                            int E, int n) {
    int e = blockIdx.x * blockDim.x + threadIdx.x;
    if (e >= E) return;
    int is64 = g_ei64;
    int s = load_idx(ei, (size_t)e, is64);
    int d = load_idx(ei, (size_t)E + e, is64);
    if ((unsigned)s >= (unsigned)n) return;
    if ((unsigned)d >= (unsigned)n) return;
    int pos = (s < 65536) ? atomicAdd(&sc[2 * n + d], 1)
                          : atomicAdd(&sc[3 * n + d], 1);
    if ((unsigned)pos < (unsigned)E_MAX)
        g_csr_lo[pos] = (unsigned short)(s & 0xFFFF);
}

// ---------------- GEMM1 (register-blocked, reduction-free) -------------------
// 64 threads/block, 256 rows/block. Thread t owns rows {t, t+64, t+128, t+192},
// all 16 output cols (16 named float4 accumulators). x staged in smem, stride
// 36 floats -> conflict-free LDS.128. W tile broadcast from smem. No shuffles.
#define GR   256
#define GK   32
#define XPAD 36

__device__ __forceinline__ void g1_store(int r, int n,
                                         float4 c0, float4 c1, float4 c2, float4 c3) {
    if (r >= n) return;
    float d = node_dis(r);
    float4* hp = (float4*)(g_hbuf + (size_t)r * HID);
    hp[0] = make_float4(d*c0.x, d*c0.y, d*c0.z, d*c0.w);
    hp[1] = make_float4(d*c1.x, d*c1.y, d*c1.z, d*c1.w);
    hp[2] = make_float4(d*c2.x, d*c2.y, d*c2.z, d*c2.w);
    hp[3] = make_float4(d*c3.x, d*c3.y, d*c3.z, d*c3.w);
}

__global__ __launch_bounds__(64) void gemm1_kernel(
    const float* __restrict__ x, const float* __restrict__ W1, int n)
{
    __shared__ float x_s[GR * XPAD];   // 36.9 KB
    __shared__ float w_s[GK * HID];    // 2 KB

    int t = threadIdx.x;
    int rbase = blockIdx.x * GR;

    float4 z = make_float4(0.f, 0.f, 0.f, 0.f);
    float4 a0_0=z, a0_1=z, a0_2=z, a0_3=z;   // row t
    float4 a1_0=z, a1_1=z, a1_2=z, a1_3=z;   // row t+64
    float4 a2_0=z, a2_1=z, a2_2=z, a2_3=z;   // row t+128
    float4 a3_0=z, a3_1=z, a3_2=z, a3_3=z;   // row t+192

    for (int kt = 0; kt < IN_F; kt += GK) {
        // stage W tile: GK*16 = 512 floats = 128 float4, 64 threads x 2
        {
            const float4* wg = (const float4*)(W1 + kt * HID);
            ((float4*)w_s)[t]      = wg[t];
            ((float4*)w_s)[t + 64] = wg[t + 64];
        }
        // stage x tile: 256 rows x 32 cols = 2048 float4; 64 threads x 32
#pragma unroll
        for (int p = 0; p < 32; p++) {
            int f   = p * 64 + t;          // f4 index
            int row = f >> 3, c4 = f & 7;
            int gr  = min(rbase + row, n - 1);
            float4 v = ((const float4*)(x + (size_t)gr * IN_F + kt))[c4];
            *(float4*)&x_s[row * XPAD + c4 * 4] = v;
        }
        __syncthreads();

#define FMA4(A, S, W) { A.x += (S)*(W).x; A.y += (S)*(W).y; A.z += (S)*(W).z; A.w += (S)*(W).w; }
#define KSTEP(KK, C) { \
        float4 w0 = *(const float4*)&w_s[(KK)*HID +  0]; \
        float4 w1 = *(const float4*)&w_s[(KK)*HID +  4]; \
        float4 w2 = *(const float4*)&w_s[(KK)*HID +  8]; \
        float4 w3 = *(const float4*)&w_s[(KK)*HID + 12]; \
        FMA4(a0_0, xv0.C, w0) FMA4(a0_1, xv0.C, w1) FMA4(a0_2, xv0.C, w2) FMA4(a0_3, xv0.C, w3) \
        FMA4(a1_0, xv1.C, w0) FMA4(a1_1, xv1.C, w1) FMA4(a1_2, xv1.C, w2) FMA4(a1_3, xv1.C, w3) \
        FMA4(a2_0, xv2.C, w0) FMA4(a2_1, xv2.C, w1) FMA4(a2_2, xv2.C, w2) FMA4(a2_3, xv2.C, w3) \
        FMA4(a3_0, xv3.C, w0) FMA4(a3_1, xv3.C, w1) FMA4(a3_2, xv3.C, w2) FMA4(a3_3, xv3.C, w3) }
#define SUB(K4) { \
        float4 xv0 = *(const float4*)&x_s[(t      ) * XPAD + (K4)]; \
        float4 xv1 = *(const float4*)&x_s[(t +  64) * XPAD + (K4)]; \
        float4 xv2 = *(const float4*)&x_s[(t + 128) * XPAD + (K4)]; \
        float4 xv3 = *(const float4*)&x_s[(t + 192) * XPAD + (K4)]; \
        KSTEP((K4)+0, x) KSTEP((K4)+1, y) KSTEP((K4)+2, z) KSTEP((K4)+3, w) }

        SUB(0) SUB(4) SUB(8) SUB(12) SUB(16) SUB(20) SUB(24) SUB(28)
#undef SUB
#undef KSTEP
#undef FMA4
        __syncthreads();
    }

    g1_store(rbase + t,       n, a0_0, a0_1, a0_2, a0_3);
    g1_store(rbase + t +  64, n, a1_0, a1_1, a1_2, a1_3);
    g1_store(rbase + t + 128, n, a2_0, a2_1, a2_2, a2_3);
    g1_store(rbase + t + 192, n, a3_0, a3_1, a3_2, a3_3);
}

// ---------------- quad-per-node CSR gather (4-wide, NO cross-quad shfl) ------
// 4 lanes per node; lane q owns float4 #q. Each lane scalar-loads the 4 CSR
// indices itself (same addresses across the quad -> L1 broadcast), giving 4
// independent row loads in flight without any shuffle hazards. No early
// return: i clamped so all lanes stay active for the quad softmax shfls
// (over-range lanes redundantly recompute node n-1; identical writes).
// mode 0: agg[i] = dis*(self + sum)            (layer-1 output)
// mode 1: out[i] = log_softmax(dis*(...) + b2) (fused final)
__global__ __launch_bounds__(256) void gather_kernel(
    float* __restrict__ agg, const float* __restrict__ b2, int mode, int n)
{
    int tt = blockIdx.x * blockDim.x + threadIdx.x;
    int i = min(tt >> 2, n - 1);
    int q = tt & 3;

    unsigned packed = g_rowptr[i];
    int end   = (int)(packed & RP_MASK);
    int nlow  = (int)(packed >> 22);
    int start = (i > 0) ? (int)(g_rowptr[i - 1] & RP_MASK) : 0;
    int mid   = start + nlow;
    float dis = rsqrtf((float)(end - start) + 1.0f);

    float4 v = ((const float4*)(g_hbuf + (size_t)i * HID))[q];   // self loop

    int j0 = start;
    for (; j0 + 4 <= end; j0 += 4) {
        int s0 = (int)g_csr_lo[j0 + 0] + ((j0 + 0 >= mid) ? 0x10000 : 0);
        int s1 = (int)g_csr_lo[j0 + 1] + ((j0 + 1 >= mid) ? 0x10000 : 0);
        int s2 = (int)g_csr_lo[j0 + 2] + ((j0 + 2 >= mid) ? 0x10000 : 0);
        int s3 = (int)g_csr_lo[j0 + 3] + ((j0 + 3 >= mid) ? 0x10000 : 0);
        float4 t0 = ((const float4*)(g_hbuf + (size_t)s0 * HID))[q];
        float4 t1 = ((const float4*)(g_hbuf + (size_t)s1 * HID))[q];
        float4 t2 = ((const float4*)(g_hbuf + (size_t)s2 * HID))[q];
        float4 t3 = ((const float4*)(g_hbuf + (size_t)s3 * HID))[q];
        v.x += t0.x + t1.x + t2.x + t3.x;
        v.y += t0.y + t1.y + t2.y + t3.y;
        v.z += t0.z + t1.z + t2.z + t3.z;
        v.w += t0.w + t1.w + t2.w + t3.w;
    }
    for (; j0 < end; j0++) {
        int s = (int)g_csr_lo[j0] + ((j0 >= mid) ? 0x10000 : 0);
        float4 tv = ((const float4*)(g_hbuf + (size_t)s * HID))[q];
        v.x += tv.x; v.y += tv.y; v.z += tv.z; v.w += tv.w;
    }

    v = make_float4(dis*v.x, dis*v.y, dis*v.z, dis*v.w);

    if (mode == 0) {
        ((float4*)(agg + (size_t)i * HID))[q] = v;
        return;
    }

    // fused: out = log_softmax(v + b2) across the quad's 16 values
    float4 bv = ((const float4*)b2)[q];
    v.x += bv.x; v.y += bv.y; v.z += bv.z; v.w += bv.w;

    float m = fmaxf(fmaxf(v.x, v.y), fmaxf(v.z, v.w));
    m = fmaxf(m, __shfl_xor_sync(0xffffffffu, m, 1));
    m = fmaxf(m, __shfl_xor_sync(0xffffffffu, m, 2));

    float s = expf(v.x - m) + expf(v.y - m) + expf(v.z - m) + expf(v.w - m);
    s += __shfl_xor_sync(0xffffffffu, s, 1);
    s += __shfl_xor_sync(0xffffffffu, s, 2);

    float lse = m + logf(s);
    ((float4*)(agg + (size_t)i * HID))[q] =
        make_float4(v.x - lse, v.y - lse, v.z - lse, v.w - lse);
}

// ---------------- layer 2: hbuf = hs2 = dis * (relu(agg1+b1) @ W2) -----------
__global__ void layer2_kernel(const float* __restrict__ b1,
                              const float* __restrict__ W2,
                              const float* __restrict__ agg, int n)
{
    __shared__ float W2s[HID * HID];
    __shared__ float b1s[HID];
    if (threadIdx.x < HID * HID) W2s[threadIdx.x] = W2[threadIdx.x];
    if (threadIdx.x < HID)       b1s[threadIdx.x] = b1[threadIdx.x];
    __syncthreads();

    int i = blockIdx.x * blockDim.x + threadIdx.x;
    if (i >= n) return;

    const float4* ap = (const float4*)(agg + (size_t)i * HID);
    float4 v0 = ap[0], v1 = ap[1], v2 = ap[2], v3 = ap[3];
    v0.x = fmaxf(v0.x + b1s[0],  0.f); v0.y = fmaxf(v0.y + b1s[1],  0.f);
    v0.z = fmaxf(v0.z + b1s[2],  0.f); v0.w = fmaxf(v0.w + b1s[3],  0.f);
    v1.x = fmaxf(v1.x + b1s[4],  0.f); v1.y = fmaxf(v1.y + b1s[5],  0.f);
    v1.z = fmaxf(v1.z + b1s[6],  0.f); v1.w = fmaxf(v1.w + b1s[7],  0.f);
    v2.x = fmaxf(v2.x + b1s[8],  0.f); v2.y = fmaxf(v2.y + b1s[9],  0.f);
    v2.z = fmaxf(v2.z + b1s[10], 0.f); v2.w = fmaxf(v2.w + b1s[11], 0.f);
    v3.x = fmaxf(v3.x + b1s[12], 0.f); v3.y = fmaxf(v3.y + b1s[13], 0.f);
    v3.z = fmaxf(v3.z + b1s[14], 0.f); v3.w = fmaxf(v3.w + b1s[15], 0.f);

#define DOT(J) ( v0.x*W2s[ 0*HID+(J)] + v0.y*W2s[ 1*HID+(J)] + v0.z*W2s[ 2*HID+(J)] + v0.w*W2s[ 3*HID+(J)] \
               + v1.x*W2s[ 4*HID+(J)] + v1.y*W2s[ 5*HID+(J)] + v1.z*W2s[ 6*HID+(J)] + v1.w*W2s[ 7*HID+(J)] \
               + v2.x*W2s[ 8*HID+(J)] + v2.y*W2s[ 9*HID+(J)] + v2.z*W2s[10*HID+(J)] + v2.w*W2s[11*HID+(J)] \
               + v3.x*W2s[12*HID+(J)] + v3.y*W2s[13*HID+(J)] + v3.z*W2s[14*HID+(J)] + v3.w*W2s[15*HID+(J)] )
    float4 s0 = make_float4(DOT(0),  DOT(1),  DOT(2),  DOT(3));
    float4 s1 = make_float4(DOT(4),  DOT(5),  DOT(6),  DOT(7));
    float4 s2 = make_float4(DOT(8),  DOT(9),  DOT(10), DOT(11));
    float4 s3 = make_float4(DOT(12), DOT(13), DOT(14), DOT(15));
#undef DOT

    float d = node_dis(i);
    float4* hp = (float4*)(g_hbuf + (size_t)i * HID);
    hp[0] = make_float4(d*s0.x, d*s0.y, d*s0.z, d*s0.w);
    hp[1] = make_float4(d*s1.x, d*s1.y, d*s1.z, d*s1.w);
    hp[2] = make_float4(d*s2.x, d*s2.y, d*s2.z, d*s2.w);
    hp[3] = make_float4(d*s3.x, d*s3.y, d*s3.z, d*s3.w);
}

// ---------------- launch ------------------------------------------------------
extern "C" void kernel_launch(void* const* d_in, const int* in_sizes, int n_in,
                              void* d_out, int out_size)
{
    const float* x  = nullptr;
    const void*  ei = nullptr;
    const float* W1 = nullptr;
    const float* W2 = nullptr;
    const float* b1 = nullptr;
    const float* b2 = nullptr;
    long long x_elems = 0, ei_elems = 0;

    for (int i = 0; i < n_in; i++) {
        int sz = in_sizes[i];
        if (sz >= 10000000) {                 // x (51.2M f32)
            x = (const float*)d_in[i]; x_elems = sz;
        } else if (sz >= 1000000) {           // edge_index (6.4M elems, dtype probed)
            ei = d_in[i]; ei_elems = sz;
        } else if (sz == IN_F * HID) {        // W1
            W1 = (const float*)d_in[i];
        } else if (sz == HID * HID) {         // W2
            W2 = (const float*)d_in[i];
        } else if (sz == HID) {               // b1 then b2
            if (!b1) b1 = (const float*)d_in[i];
            else     b2 = (const float*)d_in[i];
        }
    }
    if (!b2) b2 = b1;
    float* out = (float*)d_out;
    int*   sc  = (int*)d_out;                 // build-time scratch (consumed pre-gather1)

    int N = (int)(x_elems / IN_F);            // 100000
    int E = (int)(ei_elems / 2);              // 3200000
    if (E > E_MAX) E = E_MAX;

    int nb_nodes  = (N + 255) / 256;
    int nb_edges  = (E + 255) / 256;
    int nb_gemm   = (N + GR - 1) / GR;        // 256 rows per block, 64 threads
    int nb_zero   = (2 * N + 255) / 256;
    int nb_gather = (4 * N + 255) / 256;      // quad per node

    detect_ei_kernel   <<<1, 32>>>((const int*)ei);

    // CSR build (scratch in d_out; reused by both gathers)
    zero_scratch_kernel<<<nb_zero, 256>>>(sc, 2 * N);
    hist_kernel        <<<nb_edges, 256>>>(ei, sc, E, N);
    scan_block_kernel  <<<nb_nodes, 256>>>(sc, N);
    scan_bsum_kernel   <<<1, 512>>>(nb_nodes);
    finalize_kernel    <<<nb_nodes, 256>>>(sc, N);
    fill_kernel        <<<nb_edges, 256>>>(ei, sc, E, N);

    // layer 1: hs1 -> hbuf, agg1 -> d_out (overwrites scratch)
    gemm1_kernel       <<<nb_gemm, 64>>>(x, W1, N);
    gather_kernel      <<<nb_gather, 256>>>(out, b2, 0, N);

    // layer 2: hs2 -> hbuf; gather2 + bias + log_softmax fused -> d_out
    layer2_kernel      <<<nb_nodes, 256>>>(b1, W2, out, N);
    gather_kernel      <<<nb_gather, 256>>>(out, b2, 1, N);
}

// round 15
// speedup vs baseline: 2.2682x; 1.2269x over previous
#include <cuda_runtime.h>
#include <cuda_bf16.h>
#include <mma.h>

#define N_NODES 100000
#define E_MAX   3200000
#define IN_F    512
#define HID     16
#define RP_MASK 0x3FFFFFu

using namespace nvcuda;

// ---------------- scratch: 13.2 MB total statics (proven-pass budget) -------
__device__ __align__(16) unsigned short g_csr_lo[E_MAX];          // 6.4 MB
__device__ __align__(16) float          g_hbuf  [N_NODES * HID];  // 6.4 MB
__device__ unsigned int g_rowptr[N_NODES];                        // 0.4 MB: end | (nlow<<22)
__device__ int g_bsum[512];
__device__ int g_ei64;

// ---------------- helpers ---------------------------------------------------
__device__ __forceinline__ int load_idx(const void* ei, size_t elem, int is64) {
    if (is64) return (int)((const long long*)ei)[elem];
    return ((const int*)ei)[elem];
}

__device__ __forceinline__ float node_dis(int i) {
    unsigned end = g_rowptr[i] & RP_MASK;
    unsigned st  = (i > 0) ? (g_rowptr[i - 1] & RP_MASK) : 0u;
    return rsqrtf((float)(end - st) + 1.0f);   // +1 = self loop
}

// ---------------- zero scratch + edge-index dtype probe (fused) --------------
// int64 data (values < 2^31): odd int32 words all zero; int32 data: random.
__global__ void zero_detect_kernel(int* __restrict__ sc, int n2,
                                   const int* __restrict__ ei32) {
    int i = blockIdx.x * blockDim.x + threadIdx.x;
    if (i < n2) sc[i] = 0;
    if (blockIdx.x == 0 && threadIdx.x < 32) {
        int nz = 0;
        for (int k = threadIdx.x; k < 256; k += 32)
            if (ei32[2 * k + 1] != 0) nz = 1;
        nz = __any_sync(0xffffffffu, nz);
        if (threadIdx.x == 0) g_ei64 = nz ? 0 : 1;
    }
}

// ---------------- CSR build (counts/cursors live in d_out scratch) -----------
// sc ints: [0,n) = packed counts (total | nlow<<16)  [2n,3n)=cur_low  [3n,4n)=cur_high
__global__ void hist_kernel(const void* __restrict__ ei, int* __restrict__ sc,
                            int E, int n) {
    int e = blockIdx.x * blockDim.x + threadIdx.x;
    if (e >= E) return;
    int is64 = g_ei64;
    int s = load_idx(ei, (size_t)e, is64);
    int d = load_idx(ei, (size_t)E + e, is64);
    if ((unsigned)s >= (unsigned)n) return;
    if ((unsigned)d >= (unsigned)n) return;
    atomicAdd(&sc[d], 1 + ((s < 65536) ? 0x10000 : 0));   // total + nlow packed
}

__global__ __launch_bounds__(256) void scan_block_kernel(int* __restrict__ sc, int n) {
    __shared__ int s[256];
    int i = blockIdx.x * 256 + threadIdx.x;
    int v = (i < n) ? (sc[i] & 0xFFFF) : 0;               // scan totals only
    s[threadIdx.x] = v;
    __syncthreads();
#pragma unroll
    for (int off = 1; off < 256; off <<= 1) {
        int t = (threadIdx.x >= off) ? s[threadIdx.x - off] : 0;
        __syncthreads();
        s[threadIdx.x] += t;
        __syncthreads();
    }
    if (i < n) sc[2 * n + i] = s[threadIdx.x] - v;
    if (threadIdx.x == 255) g_bsum[blockIdx.x] = s[255];
}

__global__ __launch_bounds__(512) void scan_bsum_kernel(int nb) {
    __shared__ int s[512];
    int v = (threadIdx.x < nb) ? g_bsum[threadIdx.x] : 0;
    s[threadIdx.x] = v;
    __syncthreads();
#pragma unroll
    for (int off = 1; off < 512; off <<= 1) {
        int t = (threadIdx.x >= off) ? s[threadIdx.x - off] : 0;
        __syncthreads();
        s[threadIdx.x] += t;
        __syncthreads();
    }
    if (threadIdx.x < nb) g_bsum[threadIdx.x] = s[threadIdx.x] - v;
}

__global__ void finalize_kernel(int* __restrict__ sc, int n) {
    int i = blockIdx.x * blockDim.x + threadIdx.x;
    if (i >= n) return;
    int start = sc[2 * n + i] + g_bsum[i >> 8];
    int pk    = sc[i];
    int deg   = pk & 0xFFFF;
    int nlow  = pk >> 16;
    sc[2 * n + i] = start;               // cur_low
    sc[3 * n + i] = start + nlow;        // cur_high
    g_rowptr[i] = (unsigned)(start + deg) | ((unsigned)nlow << 22);
}

__global__ void fill_kernel(const void* __restrict__ ei, int* __restrict__ sc,
                            int E, int n) {
    int e = blockIdx.x * blockDim.x + threadIdx.x;
    if (e >= E) return;
    int is64 = g_ei64;
    int s = load_idx(ei, (size_t)e, is64);
    int d = load_idx(ei, (size_t)E + e, is64);
    if ((unsigned)s >= (unsigned)n) return;
    if ((unsigned)d >= (unsigned)n) return;
    int pos = (s < 65536) ? atomicAdd(&sc[2 * n + d], 1)
                          : atomicAdd(&sc[3 * n + d], 1);
    if ((unsigned)pos < (unsigned)E_MAX)
        g_csr_lo[pos] = (unsigned short)(s & 0xFFFF);
}

// ---------------- GEMM1 via tensor cores (tf32 wmma) -------------------------
// 128 threads (4 warps), 128 rows/block. Warp w owns rows [w*32, w*32+32):
// two 16x16 fp32 accumulators. K chunked by 64; x and W tf32-rounded in smem.
// DRAM-bound (~205 MB of x); epilogue applies dis via smem staging.
#define TCR 128
#define TCK 64
#define XS  68      // x_s row stride (floats): 64 + 4 pad, multiple of 4

__global__ __launch_bounds__(128) void gemm1_kernel(
    const float* __restrict__ x, const float* __restrict__ W1, int n)
{
    __shared__ float x_s[TCR * XS];    // 34.8 KB
    __shared__ float w_s[TCK * HID];   // 4 KB
    __shared__ float o_s[TCR * HID];   // 8 KB   (total 46.8 KB < 48 KB)

    int t = threadIdx.x;
    int warp = t >> 5;
    int rbase = blockIdx.x * TCR;

    wmma::fragment<wmma::accumulator, 16, 16, 8, float> acc0, acc1;
    wmma::fill_fragment(acc0, 0.0f);
    wmma::fill_fragment(acc1, 0.0f);

    for (int kt = 0; kt < IN_F; kt += TCK) {
        // stage W chunk (contiguous 64x16 floats), tf32-rounded
#pragma unroll
        for (int p = 0; p < 8; p++) {
            int idx = p * 128 + t;
            w_s[idx] = wmma::__float_to_tf32(W1[kt * HID + idx]);
        }
        // stage x chunk: 128 rows x 64 floats = 2048 float4, 16 per thread
#pragma unroll
        for (int p = 0; p < 16; p++) {
            int f   = p * 128 + t;
            int row = f >> 4, c4 = f & 15;
            int gr  = min(rbase + row, n - 1);
            float4 v = ((const float4*)(x + (size_t)gr * IN_F + kt))[c4];
            v.x = wmma::__float_to_tf32(v.x);
            v.y = wmma::__float_to_tf32(v.y);
            v.z = wmma::__float_to_tf32(v.z);
            v.w = wmma::__float_to_tf32(v.w);
            *(float4*)&x_s[row * XS + c4 * 4] = v;
        }
        __syncthreads();

#pragma unroll
        for (int kk = 0; kk < 8; kk++) {
            wmma::fragment<wmma::matrix_a, 16, 16, 8, wmma::precision::tf32, wmma::row_major> a0, a1;
            wmma::fragment<wmma::matrix_b, 16, 16, 8, wmma::precision::tf32, wmma::row_major> b;
            wmma::load_matrix_sync(b, &w_s[kk * 8 * HID], HID);
            wmma::load_matrix_sync(a0, &x_s[(warp * 32)      * XS + kk * 8], XS);
            wmma::load_matrix_sync(a1, &x_s[(warp * 32 + 16) * XS + kk * 8], XS);
            wmma::mma_sync(acc0, a0, b, acc0);
            wmma::mma_sync(acc1, a1, b, acc1);
        }
        __syncthreads();
    }

    wmma::store_matrix_sync(&o_s[(warp * 32)      * HID], acc0, HID, wmma::mem_row_major);
    wmma::store_matrix_sync(&o_s[(warp * 32 + 16) * HID], acc1, HID, wmma::mem_row_major);
    __syncthreads();

    int r = rbase + t;
    if (r < n) {
        float d = node_dis(r);
        const float4* op = (const float4*)&o_s[t * HID];
        float4* hp = (float4*)(g_hbuf + (size_t)r * HID);
        float4 c0 = op[0], c1 = op[1], c2 = op[2], c3 = op[3];
        hp[0] = make_float4(d*c0.x, d*c0.y, d*c0.z, d*c0.w);
        hp[1] = make_float4(d*c1.x, d*c1.y, d*c1.z, d*c1.w);
        hp[2] = make_float4(d*c2.x, d*c2.y, d*c2.z, d*c2.w);
        hp[3] = make_float4(d*c3.x, d*c3.y, d*c3.z, d*c3.w);
    }
}

// ---------------- quad-per-node CSR gather (4-wide, NO cross-quad shfl) ------
// mode 0: agg[i] = dis*(self + sum)            (layer-1 output)
// mode 1: out[i] = log_softmax(dis*(...) + b2) (fused final)
__global__ __launch_bounds__(256) void gather_kernel(
    float* __restrict__ agg, const float* __restrict__ b2, int mode, int n)
{
    int tt = blockIdx.x * blockDim.x + threadIdx.x;
    int i = min(tt >> 2, n - 1);
    int q = tt & 3;

    unsigned packed = g_rowptr[i];
    int end   = (int)(packed & RP_MASK);
    int nlow  = (int)(packed >> 22);
    int start = (i > 0) ? (int)(g_rowptr[i - 1] & RP_MASK) : 0;
    int mid   = start + nlow;
    float dis = rsqrtf((float)(end - start) + 1.0f);

    float4 v = ((const float4*)(g_hbuf + (size_t)i * HID))[q];   // self loop

    int j0 = start;
    for (; j0 + 4 <= end; j0 += 4) {
        int s0 = (int)g_csr_lo[j0 + 0] + ((j0 + 0 >= mid) ? 0x10000 : 0);
        int s1 = (int)g_csr_lo[j0 + 1] + ((j0 + 1 >= mid) ? 0x10000 : 0);
        int s2 = (int)g_csr_lo[j0 + 2] + ((j0 + 2 >= mid) ? 0x10000 : 0);
        int s3 = (int)g_csr_lo[j0 + 3] + ((j0 + 3 >= mid) ? 0x10000 : 0);
        float4 t0 = ((const float4*)(g_hbuf + (size_t)s0 * HID))[q];
        float4 t1 = ((const float4*)(g_hbuf + (size_t)s1 * HID))[q];
        float4 t2 = ((const float4*)(g_hbuf + (size_t)s2 * HID))[q];
        float4 t3 = ((const float4*)(g_hbuf + (size_t)s3 * HID))[q];
        v.x += t0.x + t1.x + t2.x + t3.x;
        v.y += t0.y + t1.y + t2.y + t3.y;
        v.z += t0.z + t1.z + t2.z + t3.z;
        v.w += t0.w + t1.w + t2.w + t3.w;
    }
    for (; j0 < end; j0++) {
        int s = (int)g_csr_lo[j0] + ((j0 >= mid) ? 0x10000 : 0);
        float4 tv = ((const float4*)(g_hbuf + (size_t)s * HID))[q];
        v.x += tv.x; v.y += tv.y; v.z += tv.z; v.w += tv.w;
    }

    v = make_float4(dis*v.x, dis*v.y, dis*v.z, dis*v.w);

    if (mode == 0) {
        ((float4*)(agg + (size_t)i * HID))[q] = v;
        return;
    }

    // fused: out = log_softmax(v + b2) across the quad's 16 values
    float4 bv = ((const float4*)b2)[q];
    v.x += bv.x; v.y += bv.y; v.z += bv.z; v.w += bv.w;

    float m = fmaxf(fmaxf(v.x, v.y), fmaxf(v.z, v.w));
    m = fmaxf(m, __shfl_xor_sync(0xffffffffu, m, 1));
    m = fmaxf(m, __shfl_xor_sync(0xffffffffu, m, 2));

    float s = expf(v.x - m) + expf(v.y - m) + expf(v.z - m) + expf(v.w - m);
    s += __shfl_xor_sync(0xffffffffu, s, 1);
    s += __shfl_xor_sync(0xffffffffu, s, 2);

    float lse = m + logf(s);
    ((float4*)(agg + (size_t)i * HID))[q] =
        make_float4(v.x - lse, v.y - lse, v.z - lse, v.w - lse);
}

// ---------------- layer 2: hbuf = hs2 = dis * (relu(agg1+b1) @ W2) -----------
__global__ void layer2_kernel(const float* __restrict__ b1,
                              const float* __restrict__ W2,
                              const float* __restrict__ agg, int n)
{
    __shared__ float W2s[HID * HID];
    __shared__ float b1s[HID];
    if (threadIdx.x < HID * HID) W2s[threadIdx.x] = W2[threadIdx.x];
    if (threadIdx.x < HID)       b1s[threadIdx.x] = b1[threadIdx.x];
    __syncthreads();

    int i = blockIdx.x * blockDim.x + threadIdx.x;
    if (i >= n) return;

    const float4* ap = (const float4*)(agg + (size_t)i * HID);
    float4 v0 = ap[0], v1 = ap[1], v2 = ap[2], v3 = ap[3];
    v0.x = fmaxf(v0.x + b1s[0],  0.f); v0.y = fmaxf(v0.y + b1s[1],  0.f);
    v0.z = fmaxf(v0.z + b1s[2],  0.f); v0.w = fmaxf(v0.w + b1s[3],  0.f);
    v1.x = fmaxf(v1.x + b1s[4],  0.f); v1.y = fmaxf(v1.y + b1s[5],  0.f);
    v1.z = fmaxf(v1.z + b1s[6],  0.f); v1.w = fmaxf(v1.w + b1s[7],  0.f);
    v2.x = fmaxf(v2.x + b1s[8],  0.f); v2.y = fmaxf(v2.y + b1s[9],  0.f);
    v2.z = fmaxf(v2.z + b1s[10], 0.f); v2.w = fmaxf(v2.w + b1s[11], 0.f);
    v3.x = fmaxf(v3.x + b1s[12], 0.f); v3.y = fmaxf(v3.y + b1s[13], 0.f);
    v3.z = fmaxf(v3.z + b1s[14], 0.f); v3.w = fmaxf(v3.w + b1s[15], 0.f);

#define DOT(J) ( v0.x*W2s[ 0*HID+(J)] + v0.y*W2s[ 1*HID+(J)] + v0.z*W2s[ 2*HID+(J)] + v0.w*W2s[ 3*HID+(J)] \
               + v1.x*W2s[ 4*HID+(J)] + v1.y*W2s[ 5*HID+(J)] + v1.z*W2s[ 6*HID+(J)] + v1.w*W2s[ 7*HID+(J)] \
               + v2.x*W2s[ 8*HID+(J)] + v2.y*W2s[ 9*HID+(J)] + v2.z*W2s[10*HID+(J)] + v2.w*W2s[11*HID+(J)] \
               + v3.x*W2s[12*HID+(J)] + v3.y*W2s[13*HID+(J)] + v3.z*W2s[14*HID+(J)] + v3.w*W2s[15*HID+(J)] )
    float4 s0 = make_float4(DOT(0),  DOT(1),  DOT(2),  DOT(3));
    float4 s1 = make_float4(DOT(4),  DOT(5),  DOT(6),  DOT(7));
    float4 s2 = make_float4(DOT(8),  DOT(9),  DOT(10), DOT(11));
    float4 s3 = make_float4(DOT(12), DOT(13), DOT(14), DOT(15));
#undef DOT

    float d = node_dis(i);
    float4* hp = (float4*)(g_hbuf + (size_t)i * HID);
    hp[0] = make_float4(d*s0.x, d*s0.y, d*s0.z, d*s0.w);
    hp[1] = make_float4(d*s1.x, d*s1.y, d*s1.z, d*s1.w);
    hp[2] = make_float4(d*s2.x, d*s2.y, d*s2.z, d*s2.w);
    hp[3] = make_float4(d*s3.x, d*s3.y, d*s3.z, d*s3.w);
}

// ---------------- launch ------------------------------------------------------
extern "C" void kernel_launch(void* const* d_in, const int* in_sizes, int n_in,
                              void* d_out, int out_size)
{
    const float* x  = nullptr;
    const void*  ei = nullptr;
    const float* W1 = nullptr;
    const float* W2 = nullptr;
    const float* b1 = nullptr;
    const float* b2 = nullptr;
    long long x_elems = 0, ei_elems = 0;

    for (int i = 0; i < n_in; i++) {
        int sz = in_sizes[i];
        if (sz >= 10000000) {                 // x (51.2M f32)
            x = (const float*)d_in[i]; x_elems = sz;
        } else if (sz >= 1000000) {           // edge_index (6.4M elems, dtype probed)
            ei = d_in[i]; ei_elems = sz;
        } else if (sz == IN_F * HID) {        // W1
            W1 = (const float*)d_in[i];
        } else if (sz == HID * HID) {         // W2
            W2 = (const float*)d_in[i];
        } else if (sz == HID) {               // b1 then b2
            if (!b1) b1 = (const float*)d_in[i];
            else     b2 = (const float*)d_in[i];
        }
    }
    if (!b2) b2 = b1;
    float* out = (float*)d_out;
    int*   sc  = (int*)d_out;                 // build-time scratch (consumed pre-gather1)

    int N = (int)(x_elems / IN_F);            // 100000
    int E = (int)(ei_elems / 2);              // 3200000
    if (E > E_MAX) E = E_MAX;

    int nb_nodes  = (N + 255) / 256;
    int nb_edges  = (E + 255) / 256;
    int nb_gemm   = (N + TCR - 1) / TCR;      // 128 rows per block, 128 threads
    int nb_zero   = (2 * N + 255) / 256;
    int nb_gather = (4 * N + 255) / 256;      // quad per node

    // CSR build (scratch in d_out; reused by both gathers)
    zero_detect_kernel <<<nb_zero, 256>>>(sc, 2 * N, (const int*)ei);
    hist_kernel        <<<nb_edges, 256>>>(ei, sc, E, N);
    scan_block_kernel  <<<nb_nodes, 256>>>(sc, N);
    scan_bsum_kernel   <<<1, 512>>>(nb_nodes);
    finalize_kernel    <<<nb_nodes, 256>>>(sc, N);
    fill_kernel        <<<nb_edges, 256>>>(ei, sc, E, N);

    // layer 1: hs1 -> hbuf (tensor cores), agg1 -> d_out (overwrites scratch)
    gemm1_kernel       <<<nb_gemm, 128>>>(x, W1, N);
    gather_kernel      <<<nb_gather, 256>>>(out, b2, 0, N);

    // layer 2: hs2 -> hbuf; gather2 + bias + log_softmax fused -> d_out
    layer2_kernel      <<<nb_nodes, 256>>>(b1, W2, out, N);
    gather_kernel      <<<nb_gather, 256>>>(out, b2, 1, N);
}

// round 16
// speedup vs baseline: 2.4513x; 1.0808x over previous
#include <cuda_runtime.h>
#include <cuda_bf16.h>
#include <mma.h>

#define N_NODES 100000
#define E_MAX   3200000
#define IN_F    512
#define HID     16
#define RP_MASK 0x3FFFFFu

using namespace nvcuda;

// ---------------- scratch: 13.2 MB total statics (proven-pass budget) -------
__device__ __align__(16) unsigned short g_csr_lo[E_MAX];          // 6.4 MB
__device__ __align__(16) float          g_hbuf  [N_NODES * HID];  // 6.4 MB
__device__ unsigned int g_rowptr[N_NODES];                        // 0.4 MB: end | (nlow<<22)
__device__ int g_bsum[512];
__device__ int g_ei64;

// ---------------- helpers ---------------------------------------------------
__device__ __forceinline__ int load_idx(const void* ei, size_t elem, int is64) {
    if (is64) return (int)((const long long*)ei)[elem];
    return ((const int*)ei)[elem];
}

// ---------------- zero scratch + edge-index dtype probe (fused) --------------
__global__ void zero_detect_kernel(int* __restrict__ sc, int n2,
                                   const int* __restrict__ ei32) {
    int i = blockIdx.x * blockDim.x + threadIdx.x;
    if (i < n2) sc[i] = 0;
    if (blockIdx.x == 0 && threadIdx.x < 32) {
        int nz = 0;
        for (int k = threadIdx.x; k < 256; k += 32)
            if (ei32[2 * k + 1] != 0) nz = 1;
        nz = __any_sync(0xffffffffu, nz);
        if (threadIdx.x == 0) g_ei64 = nz ? 0 : 1;
    }
}

// ---------------- CSR build (counts/cursors live in d_out scratch) -----------
// sc ints: [0,n) = packed counts (total | nlow<<16)  [2n,3n)=cur_low  [3n,4n)=cur_high
// 4 edges per thread; int4 vector loads on the int32 path.
__global__ void hist_kernel(const void* __restrict__ ei, int* __restrict__ sc,
                            int E, int n) {
    int t = blockIdx.x * blockDim.x + threadIdx.x;
    int e = t * 4;
    if (e >= E) return;
    int is64 = g_ei64;
    if (!is64 && (E & 3) == 0) {
        int4 sv = *((const int4*)((const int*)ei) + t);
        int4 dv = *((const int4*)((const int*)ei + E) + t);
#define H1(S, D) if ((unsigned)(S) < (unsigned)n && (unsigned)(D) < (unsigned)n) \
        atomicAdd(&sc[D], 1 + (((S) < 65536) ? 0x10000 : 0));
        H1(sv.x, dv.x) H1(sv.y, dv.y) H1(sv.z, dv.z) H1(sv.w, dv.w)
#undef H1
    } else {
        for (int k = 0; k < 4 && e + k < E; k++) {
            int s = load_idx(ei, (size_t)e + k, is64);
            int d = load_idx(ei, (size_t)E + e + k, is64);
            if ((unsigned)s < (unsigned)n && (unsigned)d < (unsigned)n)
                atomicAdd(&sc[d], 1 + ((s < 65536) ? 0x10000 : 0));
        }
    }
}

__global__ __launch_bounds__(256) void scan_block_kernel(int* __restrict__ sc, int n) {
    __shared__ int s[256];
    int i = blockIdx.x * 256 + threadIdx.x;
    int v = (i < n) ? (sc[i] & 0xFFFF) : 0;               // scan totals only
    s[threadIdx.x] = v;
    __syncthreads();
#pragma unroll
    for (int off = 1; off < 256; off <<= 1) {
        int t = (threadIdx.x >= off) ? s[threadIdx.x - off] : 0;
        __syncthreads();
        s[threadIdx.x] += t;
        __syncthreads();
    }
    if (i < n) sc[2 * n + i] = s[threadIdx.x] - v;
    if (threadIdx.x == 255) g_bsum[blockIdx.x] = s[255];
}

__global__ __launch_bounds__(512) void scan_bsum_kernel(int nb) {
    __shared__ int s[512];
    int v = (threadIdx.x < nb) ? g_bsum[threadIdx.x] : 0;
    s[threadIdx.x] = v;
    __syncthreads();
#pragma unroll
    for (int off = 1; off < 512; off <<= 1) {
        int t = (threadIdx.x >= off) ? s[threadIdx.x - off] : 0;
        __syncthreads();
        s[threadIdx.x] += t;
        __syncthreads();
    }
    if (threadIdx.x < nb) g_bsum[threadIdx.x] = s[threadIdx.x] - v;
}

__global__ void finalize_kernel(int* __restrict__ sc, int n) {
    int i = blockIdx.x * blockDim.x + threadIdx.x;
    if (i >= n) return;
    int start = sc[2 * n + i] + g_bsum[i >> 8];
    int pk    = sc[i];
    int deg   = pk & 0xFFFF;
    int nlow  = pk >> 16;
    sc[2 * n + i] = start;               // cur_low
    sc[3 * n + i] = start + nlow;        // cur_high
    g_rowptr[i] = (unsigned)(start + deg) | ((unsigned)nlow << 22);
}

__global__ void fill_kernel(const void* __restrict__ ei, int* __restrict__ sc,
                            int E, int n) {
    int t = blockIdx.x * blockDim.x + threadIdx.x;
    int e = t * 4;
    if (e >= E) return;
    int is64 = g_ei64;
    if (!is64 && (E & 3) == 0) {
        int4 sv = *((const int4*)((const int*)ei) + t);
        int4 dv = *((const int4*)((const int*)ei + E) + t);
#define F1(S, D) if ((unsigned)(S) < (unsigned)n && (unsigned)(D) < (unsigned)n) { \
        int pos = ((S) < 65536) ? atomicAdd(&sc[2 * n + (D)], 1) \
                                : atomicAdd(&sc[3 * n + (D)], 1); \
        if ((unsigned)pos < (unsigned)E_MAX) g_csr_lo[pos] = (unsigned short)((S) & 0xFFFF); }
        F1(sv.x, dv.x) F1(sv.y, dv.y) F1(sv.z, dv.z) F1(sv.w, dv.w)
#undef F1
    } else {
        for (int k = 0; k < 4 && e + k < E; k++) {
            int s = load_idx(ei, (size_t)e + k, is64);
            int d = load_idx(ei, (size_t)E + e + k, is64);
            if ((unsigned)s >= (unsigned)n) continue;
            if ((unsigned)d >= (unsigned)n) continue;
            int pos = (s < 65536) ? atomicAdd(&sc[2 * n + d], 1)
                                  : atomicAdd(&sc[3 * n + d], 1);
            if ((unsigned)pos < (unsigned)E_MAX)
                g_csr_lo[pos] = (unsigned short)(s & 0xFFFF);
        }
    }
}

// ---------------- GEMM1 via tensor cores (tf32 wmma) -------------------------
// Depends only on hist counts (dis = rsqrt(deg+1) from sc[r]), so it runs on a
// side stream concurrently with the scan/finalize/fill tail.
#define TCR 128
#define TCK 64
#define XS  68

__global__ __launch_bounds__(128) void gemm1_kernel(
    const float* __restrict__ x, const float* __restrict__ W1,
    const int* __restrict__ sc, int n)
{
    __shared__ float x_s[TCR * XS];    // 34.8 KB
    __shared__ float w_s[TCK * HID];   // 4 KB
    __shared__ float o_s[TCR * HID];   // 8 KB

    int t = threadIdx.x;
    int warp = t >> 5;
    int rbase = blockIdx.x * TCR;

    wmma::fragment<wmma::accumulator, 16, 16, 8, float> acc0, acc1;
    wmma::fill_fragment(acc0, 0.0f);
    wmma::fill_fragment(acc1, 0.0f);

    for (int kt = 0; kt < IN_F; kt += TCK) {
#pragma unroll
        for (int p = 0; p < 8; p++) {
            int idx = p * 128 + t;
            w_s[idx] = wmma::__float_to_tf32(W1[kt * HID + idx]);
        }
#pragma unroll
        for (int p = 0; p < 16; p++) {
            int f   = p * 128 + t;
            int row = f >> 4, c4 = f & 15;
            int gr  = min(rbase + row, n - 1);
            float4 v = ((const float4*)(x + (size_t)gr * IN_F + kt))[c4];
            v.x = wmma::__float_to_tf32(v.x);
            v.y = wmma::__float_to_tf32(v.y);
            v.z = wmma::__float_to_tf32(v.z);
            v.w = wmma::__float_to_tf32(v.w);
            *(float4*)&x_s[row * XS + c4 * 4] = v;
        }
        __syncthreads();

#pragma unroll
        for (int kk = 0; kk < 8; kk++) {
            wmma::fragment<wmma::matrix_a, 16, 16, 8, wmma::precision::tf32, wmma::row_major> a0, a1;
            wmma::fragment<wmma::matrix_b, 16, 16, 8, wmma::precision::tf32, wmma::row_major> b;
            wmma::load_matrix_sync(b, &w_s[kk * 8 * HID], HID);
            wmma::load_matrix_sync(a0, &x_s[(warp * 32)      * XS + kk * 8], XS);
            wmma::load_matrix_sync(a1, &x_s[(warp * 32 + 16) * XS + kk * 8], XS);
            wmma::mma_sync(acc0, a0, b, acc0);
            wmma::mma_sync(acc1, a1, b, acc1);
        }
        __syncthreads();
    }

    wmma::store_matrix_sync(&o_s[(warp * 32)      * HID], acc0, HID, wmma::mem_row_major);
    wmma::store_matrix_sync(&o_s[(warp * 32 + 16) * HID], acc1, HID, wmma::mem_row_major);
    __syncthreads();

    int r = rbase + t;
    if (r < n) {
        float d = rsqrtf((float)(sc[r] & 0xFFFF) + 1.0f);   // deg from hist counts
        const float4* op = (const float4*)&o_s[t * HID];
        float4* hp = (float4*)(g_hbuf + (size_t)r * HID);
        float4 c0 = op[0], c1 = op[1], c2 = op[2], c3 = op[3];
        hp[0] = make_float4(d*c0.x, d*c0.y, d*c0.z, d*c0.w);
        hp[1] = make_float4(d*c1.x, d*c1.y, d*c1.z, d*c1.w);
        hp[2] = make_float4(d*c2.x, d*c2.y, d*c2.z, d*c2.w);
        hp[3] = make_float4(d*c3.x, d*c3.y, d*c3.z, d*c3.w);
    }
}

// ---------------- quad-per-node CSR gather (4-wide, NO cross-quad shfl) ------
// mode 0: agg[i] = dis*(self + sum)            (layer-1 output)
// mode 1: out[i] = log_softmax(dis*(...) + b2) (fused final)
__global__ __launch_bounds__(256) void gather_kernel(
    float* __restrict__ agg, const float* __restrict__ b2, int mode, int n)
{
    int tt = blockIdx.x * blockDim.x + threadIdx.x;
    int i = min(tt >> 2, n - 1);
    int q = tt & 3;

    unsigned packed = g_rowptr[i];
    int end   = (int)(packed & RP_MASK);
    int nlow  = (int)(packed >> 22);
    int start = (i > 0) ? (int)(g_rowptr[i - 1] & RP_MASK) : 0;
    int mid   = start + nlow;
    float dis = rsqrtf((float)(end - start) + 1.0f);

    float4 v = ((const float4*)(g_hbuf + (size_t)i * HID))[q];   // self loop

    int j0 = start;
    for (; j0 + 4 <= end; j0 += 4) {
        int s0 = (int)g_csr_lo[j0 + 0] + ((j0 + 0 >= mid) ? 0x10000 : 0);
        int s1 = (int)g_csr_lo[j0 + 1] + ((j0 + 1 >= mid) ? 0x10000 : 0);
        int s2 = (int)g_csr_lo[j0 + 2] + ((j0 + 2 >= mid) ? 0x10000 : 0);
        int s3 = (int)g_csr_lo[j0 + 3] + ((j0 + 3 >= mid) ? 0x10000 : 0);
        float4 t0 = ((const float4*)(g_hbuf + (size_t)s0 * HID))[q];
        float4 t1 = ((const float4*)(g_hbuf + (size_t)s1 * HID))[q];
        float4 t2 = ((const float4*)(g_hbuf + (size_t)s2 * HID))[q];
        float4 t3 = ((const float4*)(g_hbuf + (size_t)s3 * HID))[q];
        v.x += t0.x + t1.x + t2.x + t3.x;
        v.y += t0.y + t1.y + t2.y + t3.y;
        v.z += t0.z + t1.z + t2.z + t3.z;
        v.w += t0.w + t1.w + t2.w + t3.w;
    }
    for (; j0 < end; j0++) {
        int s = (int)g_csr_lo[j0] + ((j0 >= mid) ? 0x10000 : 0);
        float4 tv = ((const float4*)(g_hbuf + (size_t)s * HID))[q];
        v.x += tv.x; v.y += tv.y; v.z += tv.z; v.w += tv.w;
    }

    v = make_float4(dis*v.x, dis*v.y, dis*v.z, dis*v.w);

    if (mode == 0) {
        ((float4*)(agg + (size_t)i * HID))[q] = v;
        return;
    }

    float4 bv = ((const float4*)b2)[q];
    v.x += bv.x; v.y += bv.y; v.z += bv.z; v.w += bv.w;

    float m = fmaxf(fmaxf(v.x, v.y), fmaxf(v.z, v.w));
    m = fmaxf(m, __shfl_xor_sync(0xffffffffu, m, 1));
    m = fmaxf(m, __shfl_xor_sync(0xffffffffu, m, 2));

    float s = expf(v.x - m) + expf(v.y - m) + expf(v.z - m) + expf(v.w - m);
    s += __shfl_xor_sync(0xffffffffu, s, 1);
    s += __shfl_xor_sync(0xffffffffu, s, 2);

    float lse = m + logf(s);
    ((float4*)(agg + (size_t)i * HID))[q] =
        make_float4(v.x - lse, v.y - lse, v.z - lse, v.w - lse);
}

// ---------------- layer 2: hbuf = hs2 = dis * (relu(agg1+b1) @ W2) -----------
__global__ void layer2_kernel(const float* __restrict__ b1,
                              const float* __restrict__ W2,
                              const float* __restrict__ agg, int n)
{
    __shared__ float W2s[HID * HID];
    __shared__ float b1s[HID];
    if (threadIdx.x < HID * HID) W2s[threadIdx.x] = W2[threadIdx.x];
    if (threadIdx.x < HID)       b1s[threadIdx.x] = b1[threadIdx.x];
    __syncthreads();

    int i = blockIdx.x * blockDim.x + threadIdx.x;
    if (i >= n) return;

    const float4* ap = (const float4*)(agg + (size_t)i * HID);
    float4 v0 = ap[0], v1 = ap[1], v2 = ap[2], v3 = ap[3];
    v0.x = fmaxf(v0.x + b1s[0],  0.f); v0.y = fmaxf(v0.y + b1s[1],  0.f);
    v0.z = fmaxf(v0.z + b1s[2],  0.f); v0.w = fmaxf(v0.w + b1s[3],  0.f);
    v1.x = fmaxf(v1.x + b1s[4],  0.f); v1.y = fmaxf(v1.y + b1s[5],  0.f);
    v1.z = fmaxf(v1.z + b1s[6],  0.f); v1.w = fmaxf(v1.w + b1s[7],  0.f);
    v2.x = fmaxf(v2.x + b1s[8],  0.f); v2.y = fmaxf(v2.y + b1s[9],  0.f);
    v2.z = fmaxf(v2.z + b1s[10], 0.f); v2.w = fmaxf(v2.w + b1s[11], 0.f);
    v3.x = fmaxf(v3.x + b1s[12], 0.f); v3.y = fmaxf(v3.y + b1s[13], 0.f);
    v3.z = fmaxf(v3.z + b1s[14], 0.f); v3.w = fmaxf(v3.w + b1s[15], 0.f);

#define DOT(J) ( v0.x*W2s[ 0*HID+(J)] + v0.y*W2s[ 1*HID+(J)] + v0.z*W2s[ 2*HID+(J)] + v0.w*W2s[ 3*HID+(J)] \
               + v1.x*W2s[ 4*HID+(J)] + v1.y*W2s[ 5*HID+(J)] + v1.z*W2s[ 6*HID+(J)] + v1.w*W2s[ 7*HID+(J)] \
               + v2.x*W2s[ 8*HID+(J)] + v2.y*W2s[ 9*HID+(J)] + v2.z*W2s[10*HID+(J)] + v2.w*W2s[11*HID+(J)] \
               + v3.x*W2s[12*HID+(J)] + v3.y*W2s[13*HID+(J)] + v3.z*W2s[14*HID+(J)] + v3.w*W2s[15*HID+(J)] )
    float4 s0 = make_float4(DOT(0),  DOT(1),  DOT(2),  DOT(3));
    float4 s1 = make_float4(DOT(4),  DOT(5),  DOT(6),  DOT(7));
    float4 s2 = make_float4(DOT(8),  DOT(9),  DOT(10), DOT(11));
    float4 s3 = make_float4(DOT(12), DOT(13), DOT(14), DOT(15));
#undef DOT

    unsigned end = g_rowptr[i] & RP_MASK;
    unsigned st  = (i > 0) ? (g_rowptr[i - 1] & RP_MASK) : 0u;
    float d = rsqrtf((float)(end - st) + 1.0f);
    float4* hp = (float4*)(g_hbuf + (size_t)i * HID);
    hp[0] = make_float4(d*s0.x, d*s0.y, d*s0.z, d*s0.w);
    hp[1] = make_float4(d*s1.x, d*s1.y, d*s1.z, d*s1.w);
    hp[2] = make_float4(d*s2.x, d*s2.y, d*s2.z, d*s2.w);
    hp[3] = make_float4(d*s3.x, d*s3.y, d*s3.z, d*s3.w);
}

// ---------------- launch ------------------------------------------------------
extern "C" void kernel_launch(void* const* d_in, const int* in_sizes, int n_in,
                              void* d_out, int out_size)
{
    const float* x  = nullptr;
    const void*  ei = nullptr;
    const float* W1 = nullptr;
    const float* W2 = nullptr;
    const float* b1 = nullptr;
    const float* b2 = nullptr;
    long long x_elems = 0, ei_elems = 0;

    for (int i = 0; i < n_in; i++) {
        int sz = in_sizes[i];
        if (sz >= 10000000) {                 // x (51.2M f32)
            x = (const float*)d_in[i]; x_elems = sz;
        } else if (sz >= 1000000) {           // edge_index (6.4M elems, dtype probed)
            ei = d_in[i]; ei_elems = sz;
        } else if (sz == IN_F * HID) {        // W1
            W1 = (const float*)d_in[i];
        } else if (sz == HID * HID) {         // W2
            W2 = (const float*)d_in[i];
        } else if (sz == HID) {               // b1 then b2
            if (!b1) b1 = (const float*)d_in[i];
            else     b2 = (const float*)d_in[i];
        }
    }
    if (!b2) b2 = b1;
    float* out = (float*)d_out;
    int*   sc  = (int*)d_out;                 // build-time scratch (consumed pre-gather1)

    int N = (int)(x_elems / IN_F);            // 100000
    int E = (int)(ei_elems / 2);              // 3200000
    if (E > E_MAX) E = E_MAX;

    int nb_nodes  = (N + 255) / 256;
    int nb_e4     = ((E + 3) / 4 + 255) / 256;   // 4 edges per thread
    int nb_gemm   = (N + TCR - 1) / TCR;
    int nb_zero   = (2 * N + 255) / 256;
    int nb_gather = (4 * N + 255) / 256;

    // side stream + fork/join events (created per call; captured into the graph)
    cudaStream_t s2;
    cudaStreamCreateWithFlags(&s2, cudaStreamNonBlocking);
    cudaEvent_t ev_hist, ev_gemm;
    cudaEventCreateWithFlags(&ev_hist, cudaEventDisableTiming);
    cudaEventCreateWithFlags(&ev_gemm, cudaEventDisableTiming);

    // main stream: counts
    zero_detect_kernel <<<nb_zero, 256>>>(sc, 2 * N, (const int*)ei);
    hist_kernel        <<<nb_e4, 256>>>(ei, sc, E, N);
    cudaEventRecord(ev_hist, 0);

    // side stream: gemm1 (needs only hist counts for dis)
    cudaStreamWaitEvent(s2, ev_hist, 0);
    gemm1_kernel       <<<nb_gemm, 128, 0, s2>>>(x, W1, sc, N);
    cudaEventRecord(ev_gemm, s2);

    // main stream: CSR scan/fill tail (concurrent with gemm1)
    scan_block_kernel  <<<nb_nodes, 256>>>(sc, N);
    scan_bsum_kernel   <<<1, 512>>>(nb_nodes);
    finalize_kernel    <<<nb_nodes, 256>>>(sc, N);
    fill_kernel        <<<nb_e4, 256>>>(ei, sc, E, N);

    // join, then the dependent chain
    cudaStreamWaitEvent(0, ev_gemm, 0);
    gather_kernel      <<<nb_gather, 256>>>(out, b2, 0, N);
    layer2_kernel      <<<nb_nodes, 256>>>(b1, W2, out, N);
    gather_kernel      <<<nb_gather, 256>>>(out, b2, 1, N);
}

// round 17
// speedup vs baseline: 2.4724x; 1.0086x over previous
#include <cuda_runtime.h>
#include <cuda_bf16.h>
#include <cuda_fp16.h>
#include <mma.h>

#define N_NODES 100000
#define E_MAX   3200000
#define IN_F    512
#define HID     16
#define RP_MASK 0x3FFFFFu

using namespace nvcuda;

// ---------------- scratch: 13.2 MB total statics (proven-pass budget) -------
__device__ __align__(16) unsigned short g_csr_lo[E_MAX];          // 6.4 MB
__device__ __align__(16) __half         g_ha[N_NODES * HID];      // 3.2 MB (hs1)
__device__ __align__(16) __half         g_hb[N_NODES * HID];      // 3.2 MB (hs2)
__device__ unsigned int g_rowptr[N_NODES];                        // 0.4 MB: end | (nlow<<22)
__device__ int g_bsum[512];
__device__ int g_ei64;

// ---------------- helpers ---------------------------------------------------
__device__ __forceinline__ int load_idx(const void* ei, size_t elem, int is64) {
    if (is64) return (int)((const long long*)ei)[elem];
    return ((const int*)ei)[elem];
}

// ---------------- zero scratch + edge-index dtype probe (fused) --------------
__global__ void zero_detect_kernel(int* __restrict__ sc, int n2,
                                   const int* __restrict__ ei32) {
    int i = blockIdx.x * blockDim.x + threadIdx.x;
    if (i < n2) sc[i] = 0;
    if (blockIdx.x == 0 && threadIdx.x < 32) {
        int nz = 0;
        for (int k = threadIdx.x; k < 256; k += 32)
            if (ei32[2 * k + 1] != 0) nz = 1;
        nz = __any_sync(0xffffffffu, nz);
        if (threadIdx.x == 0) g_ei64 = nz ? 0 : 1;
    }
}

// ---------------- CSR build (counts/cursors live in d_out scratch) -----------
// sc ints: [0,n)=packed counts (total | nlow<<16)  [2n,3n)=cur_low  [3n,4n)=cur_high
__global__ void hist_kernel(const void* __restrict__ ei, int* __restrict__ sc,
                            int E, int n) {
    int t = blockIdx.x * blockDim.x + threadIdx.x;
    int e = t * 4;
    if (e >= E) return;
    int is64 = g_ei64;
    if (!is64 && (E & 3) == 0) {
        int4 sv = *((const int4*)((const int*)ei) + t);
        int4 dv = *((const int4*)((const int*)ei + E) + t);
#define H1(S, D) if ((unsigned)(S) < (unsigned)n && (unsigned)(D) < (unsigned)n) \
        atomicAdd(&sc[D], 1 + (((S) < 65536) ? 0x10000 : 0));
        H1(sv.x, dv.x) H1(sv.y, dv.y) H1(sv.z, dv.z) H1(sv.w, dv.w)
#undef H1
    } else {
        for (int k = 0; k < 4 && e + k < E; k++) {
            int s = load_idx(ei, (size_t)e + k, is64);
            int d = load_idx(ei, (size_t)E + e + k, is64);
            if ((unsigned)s < (unsigned)n && (unsigned)d < (unsigned)n)
                atomicAdd(&sc[d], 1 + ((s < 65536) ? 0x10000 : 0));
        }
    }
}

__global__ __launch_bounds__(256) void scan_block_kernel(int* __restrict__ sc, int n) {
    __shared__ int s[256];
    int i = blockIdx.x * 256 + threadIdx.x;
    int v = (i < n) ? (sc[i] & 0xFFFF) : 0;
    s[threadIdx.x] = v;
    __syncthreads();
#pragma unroll
    for (int off = 1; off < 256; off <<= 1) {
        int t = (threadIdx.x >= off) ? s[threadIdx.x - off] : 0;
        __syncthreads();
        s[threadIdx.x] += t;
        __syncthreads();
    }
    if (i < n) sc[2 * n + i] = s[threadIdx.x] - v;
    if (threadIdx.x == 255) g_bsum[blockIdx.x] = s[255];
}

__global__ __launch_bounds__(512) void scan_bsum_kernel(int nb) {
    __shared__ int s[512];
    int v = (threadIdx.x < nb) ? g_bsum[threadIdx.x] : 0;
    s[threadIdx.x] = v;
    __syncthreads();
#pragma unroll
    for (int off = 1; off < 512; off <<= 1) {
        int t = (threadIdx.x >= off) ? s[threadIdx.x - off] : 0;
        __syncthreads();
        s[threadIdx.x] += t;
        __syncthreads();
    }
    if (threadIdx.x < nb) g_bsum[threadIdx.x] = s[threadIdx.x] - v;
}

__global__ void finalize_kernel(int* __restrict__ sc, int n) {
    int i = blockIdx.x * blockDim.x + threadIdx.x;
    if (i >= n) return;
    int start = sc[2 * n + i] + g_bsum[i >> 8];
    int pk    = sc[i];
    int deg   = pk & 0xFFFF;
    int nlow  = pk >> 16;
    sc[2 * n + i] = start;               // cur_low
    sc[3 * n + i] = start + nlow;        // cur_high
    g_rowptr[i] = (unsigned)(start + deg) | ((unsigned)nlow << 22);
}

__global__ void fill_kernel(const void* __restrict__ ei, int* __restrict__ sc,
                            int E, int n) {
    int t = blockIdx.x * blockDim.x + threadIdx.x;
    int e = t * 4;
    if (e >= E) return;
    int is64 = g_ei64;
    if (!is64 && (E & 3) == 0) {
        int4 sv = *((const int4*)((const int*)ei) + t);
        int4 dv = *((const int4*)((const int*)ei + E) + t);
#define F1(S, D) if ((unsigned)(S) < (unsigned)n && (unsigned)(D) < (unsigned)n) { \
        int pos = ((S) < 65536) ? atomicAdd(&sc[2 * n + (D)], 1) \
                                : atomicAdd(&sc[3 * n + (D)], 1); \
        if ((unsigned)pos < (unsigned)E_MAX) g_csr_lo[pos] = (unsigned short)((S) & 0xFFFF); }
        F1(sv.x, dv.x) F1(sv.y, dv.y) F1(sv.z, dv.z) F1(sv.w, dv.w)
#undef F1
    } else {
        for (int k = 0; k < 4 && e + k < E; k++) {
            int s = load_idx(ei, (size_t)e + k, is64);
            int d = load_idx(ei, (size_t)E + e + k, is64);
            if ((unsigned)s >= (unsigned)n) continue;
            if ((unsigned)d >= (unsigned)n) continue;
            int pos = (s < 65536) ? atomicAdd(&sc[2 * n + d], 1)
                                  : atomicAdd(&sc[3 * n + d], 1);
            if ((unsigned)pos < (unsigned)E_MAX)
                g_csr_lo[pos] = (unsigned short)(s & 0xFFFF);
        }
    }
}

// ---------------- GEMM1 via tensor cores (tf32 wmma), fp16 output ------------
#define TCR 128
#define TCK 64
#define XS  68

__global__ __launch_bounds__(128) void gemm1_kernel(
    const float* __restrict__ x, const float* __restrict__ W1,
    const int* __restrict__ sc, int n)
{
    __shared__ float x_s[TCR * XS];    // 34.8 KB
    __shared__ float w_s[TCK * HID];   // 4 KB
    __shared__ float o_s[TCR * HID];   // 8 KB

    int t = threadIdx.x;
    int warp = t >> 5;
    int rbase = blockIdx.x * TCR;

    wmma::fragment<wmma::accumulator, 16, 16, 8, float> acc0, acc1;
    wmma::fill_fragment(acc0, 0.0f);
    wmma::fill_fragment(acc1, 0.0f);

    for (int kt = 0; kt < IN_F; kt += TCK) {
#pragma unroll
        for (int p = 0; p < 8; p++) {
            int idx = p * 128 + t;
            w_s[idx] = wmma::__float_to_tf32(W1[kt * HID + idx]);
        }
#pragma unroll
        for (int p = 0; p < 16; p++) {
            int f   = p * 128 + t;
            int row = f >> 4, c4 = f & 15;
            int gr  = min(rbase + row, n - 1);
            float4 v = ((const float4*)(x + (size_t)gr * IN_F + kt))[c4];
            v.x = wmma::__float_to_tf32(v.x);
            v.y = wmma::__float_to_tf32(v.y);
            v.z = wmma::__float_to_tf32(v.z);
            v.w = wmma::__float_to_tf32(v.w);
            *(float4*)&x_s[row * XS + c4 * 4] = v;
        }
        __syncthreads();

#pragma unroll
        for (int kk = 0; kk < 8; kk++) {
            wmma::fragment<wmma::matrix_a, 16, 16, 8, wmma::precision::tf32, wmma::row_major> a0, a1;
            wmma::fragment<wmma::matrix_b, 16, 16, 8, wmma::precision::tf32, wmma::row_major> b;
            wmma::load_matrix_sync(b, &w_s[kk * 8 * HID], HID);
            wmma::load_matrix_sync(a0, &x_s[(warp * 32)      * XS + kk * 8], XS);
            wmma::load_matrix_sync(a1, &x_s[(warp * 32 + 16) * XS + kk * 8], XS);
            wmma::mma_sync(acc0, a0, b, acc0);
            wmma::mma_sync(acc1, a1, b, acc1);
        }
        __syncthreads();
    }

    wmma::store_matrix_sync(&o_s[(warp * 32)      * HID], acc0, HID, wmma::mem_row_major);
    wmma::store_matrix_sync(&o_s[(warp * 32 + 16) * HID], acc1, HID, wmma::mem_row_major);
    __syncthreads();

    int r = rbase + t;
    if (r < n) {
        float d = rsqrtf((float)(sc[r] & 0xFFFF) + 1.0f);   // deg from hist counts
        const float4* op = (const float4*)&o_s[t * HID];
        float4 c0 = op[0], c1 = op[1], c2 = op[2], c3 = op[3];
        __half2 h0 = __floats2half2_rn(d*c0.x, d*c0.y);
        __half2 h1 = __floats2half2_rn(d*c0.z, d*c0.w);
        __half2 h2 = __floats2half2_rn(d*c1.x, d*c1.y);
        __half2 h3 = __floats2half2_rn(d*c1.z, d*c1.w);
        __half2 h4 = __floats2half2_rn(d*c2.x, d*c2.y);
        __half2 h5 = __floats2half2_rn(d*c2.z, d*c2.w);
        __half2 h6 = __floats2half2_rn(d*c3.x, d*c3.y);
        __half2 h7 = __floats2half2_rn(d*c3.z, d*c3.w);
        uint4 u0, u1;
        u0.x = *(unsigned*)&h0; u0.y = *(unsigned*)&h1;
        u0.z = *(unsigned*)&h2; u0.w = *(unsigned*)&h3;
        u1.x = *(unsigned*)&h4; u1.y = *(unsigned*)&h5;
        u1.z = *(unsigned*)&h6; u1.w = *(unsigned*)&h7;
        uint4* hp = (uint4*)(g_ha + (size_t)r * HID);
        hp[0] = u0; hp[1] = u1;
    }
}

// ---------------- fused quad-per-node gathers (fp16 rows, 8B per lane) -------
// acc of 4 neighbor quarters from src (fp16)
__device__ __forceinline__ void acc_h(const __half* src, int s, int q, float4& v) {
    uint2 u = ((const uint2*)(src + (size_t)s * HID))[q];
    float2 f0 = __half22float2(*(__half2*)&u.x);
    float2 f1 = __half22float2(*(__half2*)&u.y);
    v.x += f0.x; v.y += f0.y; v.z += f1.x; v.w += f1.y;
}

// mode 0: read g_ha; fused layer2 (relu(agg+b1) @ W2 * dis) -> g_hb (fp16)
// mode 1: read g_hb; fused +b2 & log_softmax -> out (fp32)
__global__ __launch_bounds__(256) void gather_kernel(
    float* __restrict__ out, const float* __restrict__ b1,
    const float* __restrict__ W2, const float* __restrict__ b2,
    int mode, int n)
{
    __shared__ float W2s[HID * HID];
    if (mode == 0) W2s[threadIdx.x] = W2[threadIdx.x];   // blockDim == 256
    __syncthreads();

    int tt = blockIdx.x * blockDim.x + threadIdx.x;
    int i = min(tt >> 2, n - 1);
    int q = tt & 3;

    const __half* src = (mode == 0) ? g_ha : g_hb;

    unsigned packed = g_rowptr[i];
    int end   = (int)(packed & RP_MASK);
    int nlow  = (int)(packed >> 22);
    int start = (i > 0) ? (int)(g_rowptr[i - 1] & RP_MASK) : 0;
    int mid   = start + nlow;
    float dis = rsqrtf((float)(end - start) + 1.0f);

    float4 v = make_float4(0.f, 0.f, 0.f, 0.f);
    acc_h(src, i, q, v);                                 // self loop

    int j0 = start;
    for (; j0 + 4 <= end; j0 += 4) {
        int s0 = (int)g_csr_lo[j0 + 0] + ((j0 + 0 >= mid) ? 0x10000 : 0);
        int s1 = (int)g_csr_lo[j0 + 1] + ((j0 + 1 >= mid) ? 0x10000 : 0);
        int s2 = (int)g_csr_lo[j0 + 2] + ((j0 + 2 >= mid) ? 0x10000 : 0);
        int s3 = (int)g_csr_lo[j0 + 3] + ((j0 + 3 >= mid) ? 0x10000 : 0);
        acc_h(src, s0, q, v);
        acc_h(src, s1, q, v);
        acc_h(src, s2, q, v);
        acc_h(src, s3, q, v);
    }
    for (; j0 < end; j0++) {
        int s = (int)g_csr_lo[j0] + ((j0 >= mid) ? 0x10000 : 0);
        acc_h(src, s, q, v);
    }

    v = make_float4(dis*v.x, dis*v.y, dis*v.z, dis*v.w);  // agg quarter (fp32)

    if (mode == 0) {
        // fused layer 2: r = relu(v + b1[4q..]), o = r-partial @ W2, quad-sum
        float4 bv = ((const float4*)b1)[q];
        float r0 = fmaxf(v.x + bv.x, 0.f);
        float r1 = fmaxf(v.y + bv.y, 0.f);
        float r2 = fmaxf(v.z + bv.z, 0.f);
        float r3 = fmaxf(v.w + bv.w, 0.f);
        int k0 = q * 4;
        float4 o0, o1, o2, o3;
#define PART(J) ( r0*W2s[(k0+0)*HID+(J)] + r1*W2s[(k0+1)*HID+(J)] \
                + r2*W2s[(k0+2)*HID+(J)] + r3*W2s[(k0+3)*HID+(J)] )
        o0 = make_float4(PART(0),  PART(1),  PART(2),  PART(3));
        o1 = make_float4(PART(4),  PART(5),  PART(6),  PART(7));
        o2 = make_float4(PART(8),  PART(9),  PART(10), PART(11));
        o3 = make_float4(PART(12), PART(13), PART(14), PART(15));
#undef PART
#define QR(o) { o.x += __shfl_xor_sync(0xffffffffu, o.x, off); \
                o.y += __shfl_xor_sync(0xffffffffu, o.y, off); \
                o.z += __shfl_xor_sync(0xffffffffu, o.z, off); \
                o.w += __shfl_xor_sync(0xffffffffu, o.w, off); }
#pragma unroll
        for (int off = 1; off <= 2; off <<= 1) { QR(o0) QR(o1) QR(o2) QR(o3) }
#undef QR
        float4 mine;
        mine.x = (q == 0) ? o0.x : (q == 1) ? o1.x : (q == 2) ? o2.x : o3.x;
        mine.y = (q == 0) ? o0.y : (q == 1) ? o1.y : (q == 2) ? o2.y : o3.y;
        mine.z = (q == 0) ? o0.z : (q == 1) ? o1.z : (q == 2) ? o2.z : o3.z;
        mine.w = (q == 0) ? o0.w : (q == 1) ? o1.w : (q == 2) ? o2.w : o3.w;
        __half2 p0 = __floats2half2_rn(dis * mine.x, dis * mine.y);
        __half2 p1 = __floats2half2_rn(dis * mine.z, dis * mine.w);
        uint2 u; u.x = *(unsigned*)&p0; u.y = *(unsigned*)&p1;
        ((uint2*)(g_hb + (size_t)i * HID))[q] = u;
        return;
    }

    // mode 1: fused +b2 & log_softmax across the quad's 16 values
    float4 bv = ((const float4*)b2)[q];
    v.x += bv.x; v.y += bv.y; v.z += bv.z; v.w += bv.w;

    float m = fmaxf(fmaxf(v.x, v.y), fmaxf(v.z, v.w));
    m = fmaxf(m, __shfl_xor_sync(0xffffffffu, m, 1));
    m = fmaxf(m, __shfl_xor_sync(0xffffffffu, m, 2));

    float s = expf(v.x - m) + expf(v.y - m) + expf(v.z - m) + expf(v.w - m);
    s += __shfl_xor_sync(0xffffffffu, s, 1);
    s += __shfl_xor_sync(0xffffffffu, s, 2);

    float lse = m + logf(s);
    ((float4*)(out + (size_t)i * HID))[q] =
        make_float4(v.x - lse, v.y - lse, v.z - lse, v.w - lse);
}

// ---------------- launch ------------------------------------------------------
extern "C" void kernel_launch(void* const* d_in, const int* in_sizes, int n_in,
                              void* d_out, int out_size)
{
    const float* x  = nullptr;
    const void*  ei = nullptr;
    const float* W1 = nullptr;
    const float* W2 = nullptr;
    const float* b1 = nullptr;
    const float* b2 = nullptr;
    long long x_elems = 0, ei_elems = 0;

    for (int i = 0; i < n_in; i++) {
        int sz = in_sizes[i];
        if (sz >= 10000000) {                 // x (51.2M f32)
            x = (const float*)d_in[i]; x_elems = sz;
        } else if (sz >= 1000000) {           // edge_index (6.4M elems, dtype probed)
            ei = d_in[i]; ei_elems = sz;
        } else if (sz == IN_F * HID) {        // W1
            W1 = (const float*)d_in[i];
        } else if (sz == HID * HID) {         // W2
            W2 = (const float*)d_in[i];
        } else if (sz == HID) {               // b1 then b2
            if (!b1) b1 = (const float*)d_in[i];
            else     b2 = (const float*)d_in[i];
        }
    }
    if (!b2) b2 = b1;
    float* out = (float*)d_out;
    int*   sc  = (int*)d_out;                 // build-time scratch (consumed pre-gather1)

    int N = (int)(x_elems / IN_F);            // 100000
    int E = (int)(ei_elems / 2);              // 3200000
    if (E > E_MAX) E = E_MAX;

    int nb_nodes  = (N + 255) / 256;
    int nb_e4     = ((E + 3) / 4 + 255) / 256;
    int nb_gemm   = (N + TCR - 1) / TCR;
    int nb_zero   = (2 * N + 255) / 256;
    int nb_gather = (4 * N + 255) / 256;

    // side stream + fork/join events (captured into the graph)
    cudaStream_t s2;
    cudaStreamCreateWithFlags(&s2, cudaStreamNonBlocking);
    cudaEvent_t ev_hist, ev_gemm;
    cudaEventCreateWithFlags(&ev_hist, cudaEventDisableTiming);
    cudaEventCreateWithFlags(&ev_gemm, cudaEventDisableTiming);

    // main stream: counts
    zero_detect_kernel <<<nb_zero, 256>>>(sc, 2 * N, (const int*)ei);
    hist_kernel        <<<nb_e4, 256>>>(ei, sc, E, N);
    cudaEventRecord(ev_hist, 0);

    // side stream: gemm1 (needs only hist counts for dis)
    cudaStreamWaitEvent(s2, ev_hist, 0);
    gemm1_kernel       <<<nb_gemm, 128, 0, s2>>>(x, W1, sc, N);
    cudaEventRecord(ev_gemm, s2);

    // main stream: CSR scan/fill tail (concurrent with gemm1)
    scan_block_kernel  <<<nb_nodes, 256>>>(sc, N);
    scan_bsum_kernel   <<<1, 512>>>(nb_nodes);
    finalize_kernel    <<<nb_nodes, 256>>>(sc, N);
    fill_kernel        <<<nb_e4, 256>>>(ei, sc, E, N);

    // join, then: gather1+layer2 fused -> g_hb ; gather2+softmax fused -> out
    cudaStreamWaitEvent(0, ev_gemm, 0);
    gather_kernel      <<<nb_gather, 256>>>(out, b1, W2, b2, 0, N);
    gather_kernel      <<<nb_gather, 256>>>(out, b1, W2, b2, 1, N);
}